// round 1
// baseline (speedup 1.0000x reference)
#include <cuda_runtime.h>
#include <cuda_bf16.h>

#define N_NODES 100000
#define N_EDGES 1600000
#define IN_DIM 128
#define HID_DIM 64
#define OUT_DIM 128

// Scratch (device globals; no allocation allowed)
__device__ float g_h[N_NODES * HID_DIM];    // h_scaled = (x@Wc) * dinv[src]
__device__ float g_agg[N_NODES * HID_DIM];  // aggregated messages
__device__ float g_deg[N_NODES];
__device__ float g_dinv[N_NODES];

// ---------------------------------------------------------------------------
// Degree kernels
// ---------------------------------------------------------------------------
__global__ void k_init_deg() {
    int i = blockIdx.x * blockDim.x + threadIdx.x;
    if (i < N_NODES) g_deg[i] = 1.0f;  // self-loop
}

__global__ void k_accum_deg(const int* __restrict__ dst) {
    int e = blockIdx.x * blockDim.x + threadIdx.x;
    if (e < N_EDGES) atomicAdd(&g_deg[dst[e]], 1.0f);
}

__global__ void k_dinv() {
    int i = blockIdx.x * blockDim.x + threadIdx.x;
    if (i < N_NODES) g_dinv[i] = rsqrtf(g_deg[i]);  // deg >= 1 always
}

// ---------------------------------------------------------------------------
// GEMM1: h_scaled[n] = (x[n] @ W_conv) * dinv[n];  agg[n] = h_scaled[n]*dinv[n]
// Block: 128 threads, 128 nodes, thread-per-node, 64 accumulators.
// Shared: Ws 128x64 (32KB) + xs 32x128 transposed k-chunk (16KB) = 48KB exact.
// XOR swizzle on xs for conflict-free transpose store + read.
// ---------------------------------------------------------------------------
__global__ __launch_bounds__(128) void k_gemm1(const float* __restrict__ x,
                                               const float* __restrict__ Wc) {
    __shared__ float Ws[IN_DIM * HID_DIM];  // [k][c], 8192 floats
    __shared__ float xs[32 * 128];          // [kk][node^kk]

    const int tid = threadIdx.x;
    const int node0 = blockIdx.x * 128;
    const int n = node0 + tid;

    #pragma unroll
    for (int i = tid; i < IN_DIM * HID_DIM; i += 128) Ws[i] = Wc[i];

    float acc[HID_DIM];
    #pragma unroll
    for (int c = 0; c < HID_DIM; c++) acc[c] = 0.0f;

    for (int kc = 0; kc < IN_DIM / 32; kc++) {
        __syncthreads();
        // Load 32-k chunk for 128 nodes, transposed with XOR swizzle.
        #pragma unroll
        for (int i = 0; i < 32; i++) {
            int idx = tid + i * 128;
            int r = idx >> 5;       // node row 0..127
            int kk = idx & 31;      // k within chunk
            int nn = node0 + r;
            float v = (nn < N_NODES) ? x[nn * IN_DIM + kc * 32 + kk] : 0.0f;
            xs[kk * 128 + (r ^ kk)] = v;
        }
        __syncthreads();

        #pragma unroll 4
        for (int kk = 0; kk < 32; kk++) {
            float xv = xs[kk * 128 + (tid ^ kk)];
            const float4* wrow = (const float4*)&Ws[(kc * 32 + kk) * HID_DIM];
            #pragma unroll
            for (int c4 = 0; c4 < HID_DIM / 4; c4++) {
                float4 w = wrow[c4];  // broadcast across warp
                acc[c4 * 4 + 0] += xv * w.x;
                acc[c4 * 4 + 1] += xv * w.y;
                acc[c4 * 4 + 2] += xv * w.z;
                acc[c4 * 4 + 3] += xv * w.w;
            }
        }
    }

    if (n < N_NODES) {
        float dv = g_dinv[n];
        float dv2 = dv * dv;
        float4* hp = (float4*)&g_h[(size_t)n * HID_DIM];
        float4* ap = (float4*)&g_agg[(size_t)n * HID_DIM];
        #pragma unroll
        for (int c4 = 0; c4 < HID_DIM / 4; c4++) {
            float4 hv, av;
            hv.x = acc[c4 * 4 + 0] * dv;
            hv.y = acc[c4 * 4 + 1] * dv;
            hv.z = acc[c4 * 4 + 2] * dv;
            hv.w = acc[c4 * 4 + 3] * dv;
            av.x = acc[c4 * 4 + 0] * dv2;  // self-loop: h*dinv^2
            av.y = acc[c4 * 4 + 1] * dv2;
            av.z = acc[c4 * 4 + 2] * dv2;
            av.w = acc[c4 * 4 + 3] * dv2;
            hp[c4] = hv;
            ap[c4] = av;
        }
    }
}

// ---------------------------------------------------------------------------
// Edge scatter: agg[dst] += h_scaled[src] * dinv[dst]
// 16 threads per edge, each does one float4 gather + one red.global.add.v4.f32
// ---------------------------------------------------------------------------
__global__ __launch_bounds__(256) void k_scatter(const int* __restrict__ ei) {
    int t = blockIdx.x * 256 + threadIdx.x;
    int e = t >> 4;
    if (e >= N_EDGES) return;
    int part = t & 15;
    int src = ei[e];
    int dst = ei[N_EDGES + e];
    float d = g_dinv[dst];
    float4 hv = *(const float4*)&g_h[(size_t)src * HID_DIM + part * 4];
    float m0 = hv.x * d, m1 = hv.y * d, m2 = hv.z * d, m3 = hv.w * d;
    float* p = &g_agg[(size_t)dst * HID_DIM + part * 4];
    asm volatile("red.global.add.v4.f32 [%0], {%1, %2, %3, %4};"
                 :: "l"(p), "f"(m0), "f"(m1), "f"(m2), "f"(m3)
                 : "memory");
}

// ---------------------------------------------------------------------------
// GEMM2: out[n] = relu(agg[n] + b_conv) @ W_lin + b_lin
// Block: 256 threads, 128 nodes; thread = (node, 64-col half); 64 accumulators.
// Shared: Wl 64x128 (32KB) + as 32x128 transposed k-chunk (16KB) = 48KB exact.
// ---------------------------------------------------------------------------
__global__ __launch_bounds__(256) void k_gemm2(const float* __restrict__ bc,
                                               const float* __restrict__ Wl,
                                               const float* __restrict__ bl,
                                               float* __restrict__ out) {
    __shared__ float Ws[HID_DIM * OUT_DIM];  // [k][c], 8192 floats
    __shared__ float as[32 * 128];           // [kk][node^kk]

    const int tid = threadIdx.x;
    const int node0 = blockIdx.x * 128;
    const int r = tid >> 1;            // node row 0..127
    const int c0 = (tid & 1) * 64;     // column half
    const int n = node0 + r;

    #pragma unroll
    for (int i = tid; i < HID_DIM * OUT_DIM; i += 256) Ws[i] = Wl[i];

    float acc[64];
    #pragma unroll
    for (int c = 0; c < 64; c++) acc[c] = 0.0f;

    for (int kc = 0; kc < HID_DIM / 32; kc++) {
        __syncthreads();
        // Load 32-k chunk of relu(agg + b_conv) for 128 nodes, transposed.
        #pragma unroll
        for (int i = 0; i < 16; i++) {
            int idx = tid + i * 256;
            int rr = idx >> 5;
            int kk = idx & 31;
            int nn = node0 + rr;
            int k = kc * 32 + kk;
            float v = 0.0f;
            if (nn < N_NODES)
                v = fmaxf(g_agg[(size_t)nn * HID_DIM + k] + bc[k], 0.0f);
            as[kk * 128 + (rr ^ kk)] = v;
        }
        __syncthreads();

        #pragma unroll 4
        for (int kk = 0; kk < 32; kk++) {
            float av = as[kk * 128 + (r ^ kk)];
            const float4* wrow =
                (const float4*)&Ws[(kc * 32 + kk) * OUT_DIM + c0];
            #pragma unroll
            for (int c4 = 0; c4 < 16; c4++) {
                float4 w = wrow[c4];
                acc[c4 * 4 + 0] += av * w.x;
                acc[c4 * 4 + 1] += av * w.y;
                acc[c4 * 4 + 2] += av * w.z;
                acc[c4 * 4 + 3] += av * w.w;
            }
        }
    }

    if (n < N_NODES) {
        const float4* blp = (const float4*)&bl[c0];
        float4* op = (float4*)&out[(size_t)n * OUT_DIM + c0];
        #pragma unroll
        for (int c4 = 0; c4 < 16; c4++) {
            float4 b = blp[c4];
            float4 o;
            o.x = acc[c4 * 4 + 0] + b.x;
            o.y = acc[c4 * 4 + 1] + b.y;
            o.z = acc[c4 * 4 + 2] + b.z;
            o.w = acc[c4 * 4 + 3] + b.w;
            op[c4] = o;
        }
    }
}

// ---------------------------------------------------------------------------
// Launch
// ---------------------------------------------------------------------------
extern "C" void kernel_launch(void* const* d_in, const int* in_sizes, int n_in,
                              void* d_out, int out_size) {
    const float* x  = (const float*)d_in[0];
    const int*   ei = (const int*)d_in[1];
    const float* Wc = (const float*)d_in[2];
    const float* bc = (const float*)d_in[3];
    const float* Wl = (const float*)d_in[4];
    const float* bl = (const float*)d_in[5];
    float* out = (float*)d_out;

    k_init_deg<<<(N_NODES + 255) / 256, 256>>>();
    k_accum_deg<<<(N_EDGES + 255) / 256, 256>>>(ei + N_EDGES);
    k_dinv<<<(N_NODES + 255) / 256, 256>>>();

    k_gemm1<<<(N_NODES + 127) / 128, 128>>>(x, Wc);

    int scatter_threads = N_EDGES * 16;
    k_scatter<<<(scatter_threads + 255) / 256, 256>>>(ei);

    k_gemm2<<<(N_NODES + 127) / 128, 256>>>(bc, Wl, bl, out);
}

// round 4
// speedup vs baseline: 1.8889x; 1.8889x over previous
#include <cuda_runtime.h>
#include <cuda_bf16.h>
#include <cstdint>

#define N_NODES 100000
#define N_EDGES 1600000
#define IN_DIM 128
#define HID_DIM 64
#define OUT_DIM 128

// ---------------------------------------------------------------------------
// Device scratch (no allocations allowed)
// ---------------------------------------------------------------------------
__device__ float g_h[N_NODES * HID_DIM];    // h_scaled = (x@Wc) * dinv
__device__ float g_agg[N_NODES * HID_DIM];  // aggregated messages
__device__ float g_deg[N_NODES];
__device__ float g_dinv[N_NODES];

// Prepacked B fragments for mma.sync m16n8k16 (col-major B fragment order).
// GEMM1 (Wc 128k x 64n): kt in [0,8), nt in [0,8): idx = (kt*8+nt)*32+lane
__device__ uint2 g_WcB_hi[8 * 8 * 32];
__device__ uint2 g_WcB_lo[8 * 8 * 32];
// GEMM2 (Wl 64k x 128n): kt in [0,4), nt in [0,16): idx = (kt*16+nt)*32+lane
__device__ uint2 g_WlB_hi[4 * 16 * 32];
__device__ uint2 g_WlB_lo[4 * 16 * 32];

// ---------------------------------------------------------------------------
// Helpers
// ---------------------------------------------------------------------------
__device__ __forceinline__ uint32_t pack_bf2(__nv_bfloat16 a, __nv_bfloat16 b) {
    __nv_bfloat162 t = __halves2bfloat162(a, b);  // a -> low, b -> high
    return *reinterpret_cast<uint32_t*>(&t);
}

// Split (a,b) fp32 pair into hi/lo bf16x2 packs.
__device__ __forceinline__ void split2(float a, float b, uint32_t& hi, uint32_t& lo) {
    __nv_bfloat16 ha = __float2bfloat16_rn(a);
    __nv_bfloat16 hb = __float2bfloat16_rn(b);
    __nv_bfloat16 la = __float2bfloat16_rn(a - __bfloat162float(ha));
    __nv_bfloat16 lb = __float2bfloat16_rn(b - __bfloat162float(hb));
    hi = pack_bf2(ha, hb);
    lo = pack_bf2(la, lb);
}

// D += A(16x16 row) * B(16x8 col), bf16 in, fp32 accum.
__device__ __forceinline__ void mma16816(float* c, uint32_t a0, uint32_t a1,
                                         uint32_t a2, uint32_t a3,
                                         uint32_t b0, uint32_t b1) {
    asm volatile(
        "mma.sync.aligned.m16n8k16.row.col.f32.bf16.bf16.f32 "
        "{%0,%1,%2,%3}, {%4,%5,%6,%7}, {%8,%9}, {%0,%1,%2,%3};"
        : "+f"(c[0]), "+f"(c[1]), "+f"(c[2]), "+f"(c[3])
        : "r"(a0), "r"(a1), "r"(a2), "r"(a3), "r"(b0), "r"(b1));
}

// ---------------------------------------------------------------------------
// Degree kernels
// ---------------------------------------------------------------------------
__global__ void k_init_deg() {
    int i = blockIdx.x * blockDim.x + threadIdx.x;
    if (i < N_NODES) g_deg[i] = 1.0f;  // self-loop
}
__global__ void k_accum_deg(const int* __restrict__ dst) {
    int e = blockIdx.x * blockDim.x + threadIdx.x;
    if (e < N_EDGES) atomicAdd(&g_deg[dst[e]], 1.0f);
}
__global__ void k_dinv() {
    int i = blockIdx.x * blockDim.x + threadIdx.x;
    if (i < N_NODES) g_dinv[i] = rsqrtf(g_deg[i]);
}

// ---------------------------------------------------------------------------
// Weight prep: pack B fragments (hi/lo bf16 split) in mma fragment order.
// B fragment m16n8k16 col-major: b0 = {B[k0][n], B[k0+1][n]}, b1 = k0+8 pair,
// with k0 = kt*16 + (lane%4)*2, n = nt*8 + lane/4.
// ---------------------------------------------------------------------------
__global__ void k_prep(const float* __restrict__ Wc, const float* __restrict__ Wl) {
    int t = blockIdx.x * blockDim.x + threadIdx.x;
    if (t < 2048) {  // Wc: 8 kt x 8 nt x 32 lanes
        int lane = t & 31, nt = (t >> 5) & 7, kt = t >> 8;
        int k0 = kt * 16 + (lane & 3) * 2;
        int n = nt * 8 + (lane >> 2);
        float w00 = Wc[k0 * HID_DIM + n];
        float w01 = Wc[(k0 + 1) * HID_DIM + n];
        float w10 = Wc[(k0 + 8) * HID_DIM + n];
        float w11 = Wc[(k0 + 9) * HID_DIM + n];
        uint2 hi, lo;
        split2(w00, w01, hi.x, lo.x);
        split2(w10, w11, hi.y, lo.y);
        g_WcB_hi[t] = hi;
        g_WcB_lo[t] = lo;
    } else if (t < 4096) {  // Wl: 4 kt x 16 nt x 32 lanes
        int u = t - 2048;
        int lane = u & 31, nt = (u >> 5) & 15, kt = u >> 9;
        int k0 = kt * 16 + (lane & 3) * 2;
        int n = nt * 8 + (lane >> 2);
        float w00 = Wl[k0 * OUT_DIM + n];
        float w01 = Wl[(k0 + 1) * OUT_DIM + n];
        float w10 = Wl[(k0 + 8) * OUT_DIM + n];
        float w11 = Wl[(k0 + 9) * OUT_DIM + n];
        uint2 hi, lo;
        split2(w00, w01, hi.x, lo.x);
        split2(w10, w11, hi.y, lo.y);
        g_WlB_hi[u] = hi;
        g_WlB_lo[u] = lo;
    }
}

// ---------------------------------------------------------------------------
// GEMM1 (HMMA): h = x @ Wc;  g_h = h*dinv, g_agg = h*dinv^2 (self-loop seed)
// Block 256 = 8 warps; warp owns 16 rows x 64 cols. K=128 -> 8 k-steps.
// Split-bf16 3-product: acc = Ah*Bh + Ah*Bl + Al*Bh.
// ---------------------------------------------------------------------------
__global__ __launch_bounds__(256) void k_gemm1_mma(const float* __restrict__ x) {
    int tid = threadIdx.x, wid = tid >> 5, lane = tid & 31;
    int rowbase = blockIdx.x * 128 + wid * 16;
    int r0 = rowbase + (lane >> 2);
    int r1 = r0 + 8;
    int kc = (lane & 3) * 2;
    bool v0 = r0 < N_NODES, v1 = r1 < N_NODES;

    float acc[8][4];
    #pragma unroll
    for (int nt = 0; nt < 8; nt++)
        #pragma unroll
        for (int i = 0; i < 4; i++) acc[nt][i] = 0.0f;

    const float2 z2 = make_float2(0.f, 0.f);
    #pragma unroll
    for (int kt = 0; kt < 8; kt++) {
        int k0 = kt * 16 + kc;
        float2 x00 = v0 ? *(const float2*)&x[(size_t)r0 * IN_DIM + k0] : z2;
        float2 x02 = v0 ? *(const float2*)&x[(size_t)r0 * IN_DIM + k0 + 8] : z2;
        float2 x10 = v1 ? *(const float2*)&x[(size_t)r1 * IN_DIM + k0] : z2;
        float2 x12 = v1 ? *(const float2*)&x[(size_t)r1 * IN_DIM + k0 + 8] : z2;
        uint32_t ah0, al0, ah1, al1, ah2, al2, ah3, al3;
        split2(x00.x, x00.y, ah0, al0);  // a0: row r0, k
        split2(x10.x, x10.y, ah1, al1);  // a1: row r1, k
        split2(x02.x, x02.y, ah2, al2);  // a2: row r0, k+8
        split2(x12.x, x12.y, ah3, al3);  // a3: row r1, k+8
        const uint2* Bh = &g_WcB_hi[kt * 256 + lane];
        const uint2* Bl = &g_WcB_lo[kt * 256 + lane];
        #pragma unroll
        for (int nt = 0; nt < 8; nt++) {
            uint2 bh = Bh[nt * 32];
            uint2 bl = Bl[nt * 32];
            mma16816(acc[nt], ah0, ah1, ah2, ah3, bh.x, bh.y);
            mma16816(acc[nt], ah0, ah1, ah2, ah3, bl.x, bl.y);
            mma16816(acc[nt], al0, al1, al2, al3, bh.x, bh.y);
        }
    }

    // Epilogue: c0,c1 -> row r0 cols (nt*8+kc, +1); c2,c3 -> row r1.
    if (v0) {
        float dv = g_dinv[r0], dv2 = dv * dv;
        #pragma unroll
        for (int nt = 0; nt < 8; nt++) {
            int c = nt * 8 + kc;
            *(float2*)&g_h[(size_t)r0 * HID_DIM + c] =
                make_float2(acc[nt][0] * dv, acc[nt][1] * dv);
            *(float2*)&g_agg[(size_t)r0 * HID_DIM + c] =
                make_float2(acc[nt][0] * dv2, acc[nt][1] * dv2);
        }
    }
    if (v1) {
        float dv = g_dinv[r1], dv2 = dv * dv;
        #pragma unroll
        for (int nt = 0; nt < 8; nt++) {
            int c = nt * 8 + kc;
            *(float2*)&g_h[(size_t)r1 * HID_DIM + c] =
                make_float2(acc[nt][2] * dv, acc[nt][3] * dv);
            *(float2*)&g_agg[(size_t)r1 * HID_DIM + c] =
                make_float2(acc[nt][2] * dv2, acc[nt][3] * dv2);
        }
    }
}

// ---------------------------------------------------------------------------
// Edge scatter: agg[dst] += h_scaled[src] * dinv[dst]
// 16 threads/edge, red.global.add.v4.f32
// ---------------------------------------------------------------------------
__global__ __launch_bounds__(256) void k_scatter(const int* __restrict__ ei) {
    int t = blockIdx.x * 256 + threadIdx.x;
    int e = t >> 4;
    if (e >= N_EDGES) return;
    int part = t & 15;
    int src = ei[e];
    int dst = ei[N_EDGES + e];
    float d = g_dinv[dst];
    float4 hv = *(const float4*)&g_h[(size_t)src * HID_DIM + part * 4];
    float m0 = hv.x * d, m1 = hv.y * d, m2 = hv.z * d, m3 = hv.w * d;
    float* p = &g_agg[(size_t)dst * HID_DIM + part * 4];
    asm volatile("red.global.add.v4.f32 [%0], {%1, %2, %3, %4};"
                 :: "l"(p), "f"(m0), "f"(m1), "f"(m2), "f"(m3)
                 : "memory");
}

// ---------------------------------------------------------------------------
// GEMM2 (HMMA): out = relu(agg + bc) @ Wl + bl
// Block 256 = 8 warps; warp owns 16 rows x 128 cols. K=64 -> 4 k-steps.
// ---------------------------------------------------------------------------
__global__ __launch_bounds__(256) void k_gemm2_mma(const float* __restrict__ bc,
                                                   const float* __restrict__ bl,
                                                   float* __restrict__ out) {
    int tid = threadIdx.x, wid = tid >> 5, lane = tid & 31;
    int rowbase = blockIdx.x * 128 + wid * 16;
    int r0 = rowbase + (lane >> 2);
    int r1 = r0 + 8;
    int kc = (lane & 3) * 2;
    bool v0 = r0 < N_NODES, v1 = r1 < N_NODES;

    float acc[16][4];
    #pragma unroll
    for (int nt = 0; nt < 16; nt++)
        #pragma unroll
        for (int i = 0; i < 4; i++) acc[nt][i] = 0.0f;

    const float2 z2 = make_float2(0.f, 0.f);
    #pragma unroll
    for (int kt = 0; kt < 4; kt++) {
        int k0 = kt * 16 + kc;
        float2 bca = *(const float2*)&bc[k0];
        float2 bcb = *(const float2*)&bc[k0 + 8];
        float2 a00 = v0 ? *(const float2*)&g_agg[(size_t)r0 * HID_DIM + k0] : z2;
        float2 a02 = v0 ? *(const float2*)&g_agg[(size_t)r0 * HID_DIM + k0 + 8] : z2;
        float2 a10 = v1 ? *(const float2*)&g_agg[(size_t)r1 * HID_DIM + k0] : z2;
        float2 a12 = v1 ? *(const float2*)&g_agg[(size_t)r1 * HID_DIM + k0 + 8] : z2;
        a00.x = fmaxf(a00.x + bca.x, 0.f); a00.y = fmaxf(a00.y + bca.y, 0.f);
        a02.x = fmaxf(a02.x + bcb.x, 0.f); a02.y = fmaxf(a02.y + bcb.y, 0.f);
        a10.x = fmaxf(a10.x + bca.x, 0.f); a10.y = fmaxf(a10.y + bca.y, 0.f);
        a12.x = fmaxf(a12.x + bcb.x, 0.f); a12.y = fmaxf(a12.y + bcb.y, 0.f);
        if (!v0) { a00 = z2; a02 = z2; }
        if (!v1) { a10 = z2; a12 = z2; }
        uint32_t ah0, al0, ah1, al1, ah2, al2, ah3, al3;
        split2(a00.x, a00.y, ah0, al0);
        split2(a10.x, a10.y, ah1, al1);
        split2(a02.x, a02.y, ah2, al2);
        split2(a12.x, a12.y, ah3, al3);
        const uint2* Bh = &g_WlB_hi[kt * 512 + lane];
        const uint2* Bl = &g_WlB_lo[kt * 512 + lane];
        #pragma unroll
        for (int nt = 0; nt < 16; nt++) {
            uint2 bh = Bh[nt * 32];
            uint2 blf = Bl[nt * 32];
            mma16816(acc[nt], ah0, ah1, ah2, ah3, bh.x, bh.y);
            mma16816(acc[nt], ah0, ah1, ah2, ah3, blf.x, blf.y);
            mma16816(acc[nt], al0, al1, al2, al3, bh.x, bh.y);
        }
    }

    if (v0) {
        #pragma unroll
        for (int nt = 0; nt < 16; nt++) {
            int c = nt * 8 + kc;
            float2 b = *(const float2*)&bl[c];
            *(float2*)&out[(size_t)r0 * OUT_DIM + c] =
                make_float2(acc[nt][0] + b.x, acc[nt][1] + b.y);
        }
    }
    if (v1) {
        #pragma unroll
        for (int nt = 0; nt < 16; nt++) {
            int c = nt * 8 + kc;
            float2 b = *(const float2*)&bl[c];
            *(float2*)&out[(size_t)r1 * OUT_DIM + c] =
                make_float2(acc[nt][2] + b.x, acc[nt][3] + b.y);
        }
    }
}

// ---------------------------------------------------------------------------
// Launch
// ---------------------------------------------------------------------------
extern "C" void kernel_launch(void* const* d_in, const int* in_sizes, int n_in,
                              void* d_out, int out_size) {
    const float* x  = (const float*)d_in[0];
    const int*   ei = (const int*)d_in[1];
    const float* Wc = (const float*)d_in[2];
    const float* bc = (const float*)d_in[3];
    const float* Wl = (const float*)d_in[4];
    const float* bl = (const float*)d_in[5];
    float* out = (float*)d_out;

    k_prep<<<16, 256>>>(Wc, Wl);
    k_init_deg<<<(N_NODES + 255) / 256, 256>>>();
    k_accum_deg<<<(N_EDGES + 255) / 256, 256>>>(ei + N_EDGES);
    k_dinv<<<(N_NODES + 255) / 256, 256>>>();

    int grid = (N_NODES + 127) / 128;  // 782
    k_gemm1_mma<<<grid, 256>>>(x);

    int scatter_threads = N_EDGES * 16;
    k_scatter<<<(scatter_threads + 255) / 256, 256>>>(ei);

    k_gemm2_mma<<<grid, 256>>>(bc, bl, out);
}

// round 5
// speedup vs baseline: 2.1385x; 1.1321x over previous
#include <cuda_runtime.h>
#include <cuda_bf16.h>
#include <cstdint>

#define N_NODES 100000
#define N_EDGES 1600000
#define IN_DIM 128
#define HID_DIM 64
#define OUT_DIM 128

#define SCAN_NB 98  // ceil(100000/1024)

// ---------------------------------------------------------------------------
// Device scratch (no allocations allowed)
// ---------------------------------------------------------------------------
__device__ float g_h[N_NODES * HID_DIM];    // h_scaled = (x@Wc) * dinv[row]
__device__ float g_agg[N_NODES * HID_DIM];  // aggregated messages
__device__ float g_dinv[N_NODES];
__device__ int   g_cnt[N_NODES];            // in-degree (no self-loop)
__device__ int   g_off[N_NODES];            // CSR row start
__device__ int   g_cur[N_NODES];            // binning cursor
__device__ int   g_bsum[SCAN_NB];           // scan block sums
__device__ int   g_boff[SCAN_NB];           // scan block offsets
__device__ int   g_srcbin[N_EDGES];         // CSR: src per in-edge, grouped by dst

// Prepacked B fragments for mma.sync m16n8k16 (col-major B fragment order).
__device__ uint2 g_WcB_hi[8 * 8 * 32];
__device__ uint2 g_WcB_lo[8 * 8 * 32];
__device__ uint2 g_WlB_hi[4 * 16 * 32];
__device__ uint2 g_WlB_lo[4 * 16 * 32];

// ---------------------------------------------------------------------------
// Helpers
// ---------------------------------------------------------------------------
__device__ __forceinline__ uint32_t pack_bf2(__nv_bfloat16 a, __nv_bfloat16 b) {
    __nv_bfloat162 t = __halves2bfloat162(a, b);
    return *reinterpret_cast<uint32_t*>(&t);
}

__device__ __forceinline__ void split2(float a, float b, uint32_t& hi, uint32_t& lo) {
    __nv_bfloat16 ha = __float2bfloat16_rn(a);
    __nv_bfloat16 hb = __float2bfloat16_rn(b);
    __nv_bfloat16 la = __float2bfloat16_rn(a - __bfloat162float(ha));
    __nv_bfloat16 lb = __float2bfloat16_rn(b - __bfloat162float(hb));
    hi = pack_bf2(ha, hb);
    lo = pack_bf2(la, lb);
}

__device__ __forceinline__ void mma16816(float* c, uint32_t a0, uint32_t a1,
                                         uint32_t a2, uint32_t a3,
                                         uint32_t b0, uint32_t b1) {
    asm volatile(
        "mma.sync.aligned.m16n8k16.row.col.f32.bf16.bf16.f32 "
        "{%0,%1,%2,%3}, {%4,%5,%6,%7}, {%8,%9}, {%0,%1,%2,%3};"
        : "+f"(c[0]), "+f"(c[1]), "+f"(c[2]), "+f"(c[3])
        : "r"(a0), "r"(a1), "r"(a2), "r"(a3), "r"(b0), "r"(b1));
}

// ---------------------------------------------------------------------------
// Degree counting + dinv
// ---------------------------------------------------------------------------
__global__ void k_zero_cnt() {
    int i = blockIdx.x * blockDim.x + threadIdx.x;
    if (i < N_NODES) g_cnt[i] = 0;
}
__global__ void k_count(const int* __restrict__ dst) {
    int e = blockIdx.x * blockDim.x + threadIdx.x;
    if (e < N_EDGES) atomicAdd(&g_cnt[dst[e]], 1);
}
__global__ void k_dinv() {
    int i = blockIdx.x * blockDim.x + threadIdx.x;
    if (i < N_NODES) g_dinv[i] = rsqrtf((float)(g_cnt[i] + 1));  // +1 self-loop
}

// ---------------------------------------------------------------------------
// Exclusive scan of g_cnt -> g_off (3 kernels; 1024 elems per level-1 block)
// ---------------------------------------------------------------------------
__global__ __launch_bounds__(256) void k_scan1() {
    __shared__ int sh[256];
    int t = threadIdx.x;
    int base = blockIdx.x * 1024 + t * 4;
    int v[4];
    #pragma unroll
    for (int i = 0; i < 4; i++)
        v[i] = (base + i < N_NODES) ? g_cnt[base + i] : 0;
    int s = v[0] + v[1] + v[2] + v[3];
    sh[t] = s;
    __syncthreads();
    #pragma unroll
    for (int off = 1; off < 256; off <<= 1) {
        int add = (t >= off) ? sh[t - off] : 0;
        __syncthreads();
        sh[t] += add;
        __syncthreads();
    }
    int ex = sh[t] - s;  // exclusive prefix within block
    int run = ex;
    #pragma unroll
    for (int i = 0; i < 4; i++) {
        if (base + i < N_NODES) g_off[base + i] = run;
        run += v[i];
    }
    if (t == 255) g_bsum[blockIdx.x] = sh[255];
}

__global__ __launch_bounds__(128) void k_scan2() {
    __shared__ int sh[128];
    int t = threadIdx.x;
    int s = (t < SCAN_NB) ? g_bsum[t] : 0;
    sh[t] = s;
    __syncthreads();
    #pragma unroll
    for (int off = 1; off < 128; off <<= 1) {
        int add = (t >= off) ? sh[t - off] : 0;
        __syncthreads();
        sh[t] += add;
        __syncthreads();
    }
    if (t < SCAN_NB) g_boff[t] = sh[t] - s;
}

__global__ __launch_bounds__(256) void k_scan3() {
    int boff = g_boff[blockIdx.x];
    int base = blockIdx.x * 1024 + threadIdx.x * 4;
    #pragma unroll
    for (int i = 0; i < 4; i++) {
        int idx = base + i;
        if (idx < N_NODES) {
            int o = g_off[idx] + boff;
            g_off[idx] = o;
            g_cur[idx] = o;
        }
    }
}

// ---------------------------------------------------------------------------
// Bin edges by dst (CSR build)
// ---------------------------------------------------------------------------
__global__ void k_bin(const int* __restrict__ ei) {
    int e = blockIdx.x * blockDim.x + threadIdx.x;
    if (e >= N_EDGES) return;
    int src = ei[e];
    int dst = ei[N_EDGES + e];
    int pos = atomicAdd(&g_cur[dst], 1);
    g_srcbin[pos] = src;
}

// ---------------------------------------------------------------------------
// Weight prep (fragment packing, hi/lo bf16 split)
// ---------------------------------------------------------------------------
__global__ void k_prep(const float* __restrict__ Wc, const float* __restrict__ Wl) {
    int t = blockIdx.x * blockDim.x + threadIdx.x;
    if (t < 2048) {  // Wc: 8 kt x 8 nt x 32 lanes
        int lane = t & 31, nt = (t >> 5) & 7, kt = t >> 8;
        int k0 = kt * 16 + (lane & 3) * 2;
        int n = nt * 8 + (lane >> 2);
        float w00 = Wc[k0 * HID_DIM + n];
        float w01 = Wc[(k0 + 1) * HID_DIM + n];
        float w10 = Wc[(k0 + 8) * HID_DIM + n];
        float w11 = Wc[(k0 + 9) * HID_DIM + n];
        uint2 hi, lo;
        split2(w00, w01, hi.x, lo.x);
        split2(w10, w11, hi.y, lo.y);
        g_WcB_hi[t] = hi;
        g_WcB_lo[t] = lo;
    } else if (t < 4096) {  // Wl: 4 kt x 16 nt x 32 lanes
        int u = t - 2048;
        int lane = u & 31, nt = (u >> 5) & 15, kt = u >> 9;
        int k0 = kt * 16 + (lane & 3) * 2;
        int n = nt * 8 + (lane >> 2);
        float w00 = Wl[k0 * OUT_DIM + n];
        float w01 = Wl[(k0 + 1) * OUT_DIM + n];
        float w10 = Wl[(k0 + 8) * OUT_DIM + n];
        float w11 = Wl[(k0 + 9) * OUT_DIM + n];
        uint2 hi, lo;
        split2(w00, w01, hi.x, lo.x);
        split2(w10, w11, hi.y, lo.y);
        g_WlB_hi[u] = hi;
        g_WlB_lo[u] = lo;
    }
}

// ---------------------------------------------------------------------------
// GEMM1 (HMMA): g_h = (x @ Wc) * dinv[row]
// ---------------------------------------------------------------------------
__global__ __launch_bounds__(256) void k_gemm1_mma(const float* __restrict__ x) {
    int tid = threadIdx.x, wid = tid >> 5, lane = tid & 31;
    int rowbase = blockIdx.x * 128 + wid * 16;
    int r0 = rowbase + (lane >> 2);
    int r1 = r0 + 8;
    int kc = (lane & 3) * 2;
    bool v0 = r0 < N_NODES, v1 = r1 < N_NODES;

    float acc[8][4];
    #pragma unroll
    for (int nt = 0; nt < 8; nt++)
        #pragma unroll
        for (int i = 0; i < 4; i++) acc[nt][i] = 0.0f;

    const float2 z2 = make_float2(0.f, 0.f);
    #pragma unroll
    for (int kt = 0; kt < 8; kt++) {
        int k0 = kt * 16 + kc;
        float2 x00 = v0 ? *(const float2*)&x[(size_t)r0 * IN_DIM + k0] : z2;
        float2 x02 = v0 ? *(const float2*)&x[(size_t)r0 * IN_DIM + k0 + 8] : z2;
        float2 x10 = v1 ? *(const float2*)&x[(size_t)r1 * IN_DIM + k0] : z2;
        float2 x12 = v1 ? *(const float2*)&x[(size_t)r1 * IN_DIM + k0 + 8] : z2;
        uint32_t ah0, al0, ah1, al1, ah2, al2, ah3, al3;
        split2(x00.x, x00.y, ah0, al0);
        split2(x10.x, x10.y, ah1, al1);
        split2(x02.x, x02.y, ah2, al2);
        split2(x12.x, x12.y, ah3, al3);
        const uint2* Bh = &g_WcB_hi[kt * 256 + lane];
        const uint2* Bl = &g_WcB_lo[kt * 256 + lane];
        #pragma unroll
        for (int nt = 0; nt < 8; nt++) {
            uint2 bh = Bh[nt * 32];
            uint2 bl = Bl[nt * 32];
            mma16816(acc[nt], ah0, ah1, ah2, ah3, bh.x, bh.y);
            mma16816(acc[nt], ah0, ah1, ah2, ah3, bl.x, bl.y);
            mma16816(acc[nt], al0, al1, al2, al3, bh.x, bh.y);
        }
    }

    if (v0) {
        float dv = g_dinv[r0];
        #pragma unroll
        for (int nt = 0; nt < 8; nt++) {
            int c = nt * 8 + kc;
            *(float2*)&g_h[(size_t)r0 * HID_DIM + c] =
                make_float2(acc[nt][0] * dv, acc[nt][1] * dv);
        }
    }
    if (v1) {
        float dv = g_dinv[r1];
        #pragma unroll
        for (int nt = 0; nt < 8; nt++) {
            int c = nt * 8 + kc;
            *(float2*)&g_h[(size_t)r1 * HID_DIM + c] =
                make_float2(acc[nt][2] * dv, acc[nt][3] * dv);
        }
    }
}

// ---------------------------------------------------------------------------
// CSR aggregate (atomic-free):
// agg[n] = (sum_{src in in(n)} g_h[src] + g_h[n]) * dinv[n]
// Block 256 = 16 nodes x 16 threads; thread owns 4 of 64 cols.
// ---------------------------------------------------------------------------
__global__ __launch_bounds__(256) void k_aggregate() {
    int tid = threadIdx.x;
    int node = blockIdx.x * 16 + (tid >> 4);
    int part = tid & 15;
    if (node >= N_NODES) return;

    int beg = g_off[node];
    int end = beg + g_cnt[node];

    // self-loop term: g_h[n] (= h_n * dinv_n)
    float4 acc = *(const float4*)&g_h[(size_t)node * HID_DIM + part * 4];

    for (int p = beg; p < end; p += 16) {
        int mye = p + part;
        int mysrc = (mye < end) ? g_srcbin[mye] : 0;
        int m = end - p;  // >=1
        #pragma unroll
        for (int j = 0; j < 16; j++) {
            if (j < m) {
                int s = __shfl_sync(0xffffffffu, mysrc, j, 16);
                float4 hv = *(const float4*)&g_h[(size_t)s * HID_DIM + part * 4];
                acc.x += hv.x; acc.y += hv.y; acc.z += hv.z; acc.w += hv.w;
            }
        }
    }

    float dv = g_dinv[node];
    acc.x *= dv; acc.y *= dv; acc.z *= dv; acc.w *= dv;
    *(float4*)&g_agg[(size_t)node * HID_DIM + part * 4] = acc;
}

// ---------------------------------------------------------------------------
// GEMM2 (HMMA): out = relu(agg + bc) @ Wl + bl
// ---------------------------------------------------------------------------
__global__ __launch_bounds__(256) void k_gemm2_mma(const float* __restrict__ bc,
                                                   const float* __restrict__ bl,
                                                   float* __restrict__ out) {
    int tid = threadIdx.x, wid = tid >> 5, lane = tid & 31;
    int rowbase = blockIdx.x * 128 + wid * 16;
    int r0 = rowbase + (lane >> 2);
    int r1 = r0 + 8;
    int kc = (lane & 3) * 2;
    bool v0 = r0 < N_NODES, v1 = r1 < N_NODES;

    float acc[16][4];
    #pragma unroll
    for (int nt = 0; nt < 16; nt++)
        #pragma unroll
        for (int i = 0; i < 4; i++) acc[nt][i] = 0.0f;

    const float2 z2 = make_float2(0.f, 0.f);
    #pragma unroll
    for (int kt = 0; kt < 4; kt++) {
        int k0 = kt * 16 + kc;
        float2 bca = *(const float2*)&bc[k0];
        float2 bcb = *(const float2*)&bc[k0 + 8];
        float2 a00 = v0 ? *(const float2*)&g_agg[(size_t)r0 * HID_DIM + k0] : z2;
        float2 a02 = v0 ? *(const float2*)&g_agg[(size_t)r0 * HID_DIM + k0 + 8] : z2;
        float2 a10 = v1 ? *(const float2*)&g_agg[(size_t)r1 * HID_DIM + k0] : z2;
        float2 a12 = v1 ? *(const float2*)&g_agg[(size_t)r1 * HID_DIM + k0 + 8] : z2;
        a00.x = fmaxf(a00.x + bca.x, 0.f); a00.y = fmaxf(a00.y + bca.y, 0.f);
        a02.x = fmaxf(a02.x + bcb.x, 0.f); a02.y = fmaxf(a02.y + bcb.y, 0.f);
        a10.x = fmaxf(a10.x + bca.x, 0.f); a10.y = fmaxf(a10.y + bca.y, 0.f);
        a12.x = fmaxf(a12.x + bcb.x, 0.f); a12.y = fmaxf(a12.y + bcb.y, 0.f);
        if (!v0) { a00 = z2; a02 = z2; }
        if (!v1) { a10 = z2; a12 = z2; }
        uint32_t ah0, al0, ah1, al1, ah2, al2, ah3, al3;
        split2(a00.x, a00.y, ah0, al0);
        split2(a10.x, a10.y, ah1, al1);
        split2(a02.x, a02.y, ah2, al2);
        split2(a12.x, a12.y, ah3, al3);
        const uint2* Bh = &g_WlB_hi[kt * 512 + lane];
        const uint2* Bl = &g_WlB_lo[kt * 512 + lane];
        #pragma unroll
        for (int nt = 0; nt < 16; nt++) {
            uint2 bh = Bh[nt * 32];
            uint2 blf = Bl[nt * 32];
            mma16816(acc[nt], ah0, ah1, ah2, ah3, bh.x, bh.y);
            mma16816(acc[nt], ah0, ah1, ah2, ah3, blf.x, blf.y);
            mma16816(acc[nt], al0, al1, al2, al3, bh.x, bh.y);
        }
    }

    if (v0) {
        #pragma unroll
        for (int nt = 0; nt < 16; nt++) {
            int c = nt * 8 + kc;
            float2 b = *(const float2*)&bl[c];
            *(float2*)&out[(size_t)r0 * OUT_DIM + c] =
                make_float2(acc[nt][0] + b.x, acc[nt][1] + b.y);
        }
    }
    if (v1) {
        #pragma unroll
        for (int nt = 0; nt < 16; nt++) {
            int c = nt * 8 + kc;
            float2 b = *(const float2*)&bl[c];
            *(float2*)&out[(size_t)r1 * OUT_DIM + c] =
                make_float2(acc[nt][2] + b.x, acc[nt][3] + b.y);
        }
    }
}

// ---------------------------------------------------------------------------
// Launch
// ---------------------------------------------------------------------------
extern "C" void kernel_launch(void* const* d_in, const int* in_sizes, int n_in,
                              void* d_out, int out_size) {
    const float* x  = (const float*)d_in[0];
    const int*   ei = (const int*)d_in[1];
    const float* Wc = (const float*)d_in[2];
    const float* bc = (const float*)d_in[3];
    const float* Wl = (const float*)d_in[4];
    const float* bl = (const float*)d_in[5];
    float* out = (float*)d_out;

    k_prep<<<16, 256>>>(Wc, Wl);
    k_zero_cnt<<<(N_NODES + 255) / 256, 256>>>();
    k_count<<<(N_EDGES + 255) / 256, 256>>>(ei + N_EDGES);
    k_scan1<<<SCAN_NB, 256>>>();
    k_scan2<<<1, 128>>>();
    k_scan3<<<SCAN_NB, 256>>>();
    k_dinv<<<(N_NODES + 255) / 256, 256>>>();
    k_bin<<<(N_EDGES + 255) / 256, 256>>>(ei);

    int grid = (N_NODES + 127) / 128;  // 782
    k_gemm1_mma<<<grid, 256>>>(x);
    k_aggregate<<<(N_NODES + 15) / 16, 256>>>();
    k_gemm2_mma<<<grid, 256>>>(bc, bl, out);
}

// round 6
// speedup vs baseline: 2.4059x; 1.1250x over previous
#include <cuda_runtime.h>
#include <cuda_bf16.h>
#include <cuda_fp16.h>
#include <cstdint>

#define N_NODES 100000
#define N_EDGES 1600000
#define IN_DIM 128
#define HID_DIM 64
#define OUT_DIM 128

#define SCAN_NB 98  // ceil(100000/1024)

// ---------------------------------------------------------------------------
// Device scratch (no allocations allowed)
// ---------------------------------------------------------------------------
__device__ __half g_h16[N_NODES * HID_DIM];  // h_scaled = (x@Wc)*dinv, fp16
__device__ float  g_agg[N_NODES * HID_DIM];  // aggregated messages (fp32)
__device__ float  g_dinv[N_NODES];
__device__ int    g_cnt[N_NODES];            // in-degree (no self-loop)
__device__ int    g_off[N_NODES];            // CSR row start
__device__ int    g_cur[N_NODES];            // binning cursor
__device__ int    g_bsum[SCAN_NB];
__device__ int    g_boff[SCAN_NB];
__device__ int    g_srcbin[N_EDGES];         // CSR: src per in-edge, by dst

// Prepacked B fragments for mma.sync m16n8k16 (col-major B fragment order).
__device__ uint2 g_WcB_hi[8 * 8 * 32];
__device__ uint2 g_WcB_lo[8 * 8 * 32];
__device__ uint2 g_WlB_hi[4 * 16 * 32];
__device__ uint2 g_WlB_lo[4 * 16 * 32];

// ---------------------------------------------------------------------------
// Helpers
// ---------------------------------------------------------------------------
// Split fp32 pair (a,b) -> hi/lo bf16x2 packs (a in low half, b in high half).
__device__ __forceinline__ void split2(float a, float b, uint32_t& hi, uint32_t& lo) {
    uint32_t h;
    asm("cvt.rn.bf16x2.f32 %0, %1, %2;" : "=r"(h) : "f"(b), "f"(a));
    float fa = __uint_as_float(h << 16);
    float fb = __uint_as_float(h & 0xffff0000u);
    asm("cvt.rn.bf16x2.f32 %0, %1, %2;" : "=r"(lo) : "f"(b - fb), "f"(a - fa));
    hi = h;
}

__device__ __forceinline__ void mma16816(float* c, uint32_t a0, uint32_t a1,
                                         uint32_t a2, uint32_t a3,
                                         uint32_t b0, uint32_t b1) {
    asm volatile(
        "mma.sync.aligned.m16n8k16.row.col.f32.bf16.bf16.f32 "
        "{%0,%1,%2,%3}, {%4,%5,%6,%7}, {%8,%9}, {%0,%1,%2,%3};"
        : "+f"(c[0]), "+f"(c[1]), "+f"(c[2]), "+f"(c[3])
        : "r"(a0), "r"(a1), "r"(a2), "r"(a3), "r"(b0), "r"(b1));
}

// ---------------------------------------------------------------------------
// Init: zero degree counters + pack weight fragments (hi/lo bf16 split)
// ---------------------------------------------------------------------------
__global__ void k_init(const float* __restrict__ Wc, const float* __restrict__ Wl) {
    int t = blockIdx.x * blockDim.x + threadIdx.x;
    if (t < N_NODES) g_cnt[t] = 0;
    if (t < 2048) {  // Wc: 8 kt x 8 nt x 32 lanes
        int lane = t & 31, nt = (t >> 5) & 7, kt = t >> 8;
        int k0 = kt * 16 + (lane & 3) * 2;
        int n = nt * 8 + (lane >> 2);
        uint2 hi, lo;
        split2(Wc[k0 * HID_DIM + n], Wc[(k0 + 1) * HID_DIM + n], hi.x, lo.x);
        split2(Wc[(k0 + 8) * HID_DIM + n], Wc[(k0 + 9) * HID_DIM + n], hi.y, lo.y);
        g_WcB_hi[t] = hi;
        g_WcB_lo[t] = lo;
    } else if (t < 4096) {  // Wl: 4 kt x 16 nt x 32 lanes
        int u = t - 2048;
        int lane = u & 31, nt = (u >> 5) & 15, kt = u >> 9;
        int k0 = kt * 16 + (lane & 3) * 2;
        int n = nt * 8 + (lane >> 2);
        uint2 hi, lo;
        split2(Wl[k0 * OUT_DIM + n], Wl[(k0 + 1) * OUT_DIM + n], hi.x, lo.x);
        split2(Wl[(k0 + 8) * OUT_DIM + n], Wl[(k0 + 9) * OUT_DIM + n], hi.y, lo.y);
        g_WlB_hi[u] = hi;
        g_WlB_lo[u] = lo;
    }
}

__global__ void k_count(const int* __restrict__ dst) {
    int e = blockIdx.x * blockDim.x + threadIdx.x;
    if (e < N_EDGES) atomicAdd(&g_cnt[dst[e]], 1);
}

// ---------------------------------------------------------------------------
// Exclusive scan of g_cnt -> g_off (3 kernels; 1024 elems per level-1 block)
// ---------------------------------------------------------------------------
__global__ __launch_bounds__(256) void k_scan1() {
    __shared__ int sh[256];
    int t = threadIdx.x;
    int base = blockIdx.x * 1024 + t * 4;
    int v[4];
    #pragma unroll
    for (int i = 0; i < 4; i++)
        v[i] = (base + i < N_NODES) ? g_cnt[base + i] : 0;
    int s = v[0] + v[1] + v[2] + v[3];
    sh[t] = s;
    __syncthreads();
    #pragma unroll
    for (int off = 1; off < 256; off <<= 1) {
        int add = (t >= off) ? sh[t - off] : 0;
        __syncthreads();
        sh[t] += add;
        __syncthreads();
    }
    int run = sh[t] - s;
    #pragma unroll
    for (int i = 0; i < 4; i++) {
        if (base + i < N_NODES) g_off[base + i] = run;
        run += v[i];
    }
    if (t == 255) g_bsum[blockIdx.x] = sh[255];
}

__global__ __launch_bounds__(128) void k_scan2() {
    __shared__ int sh[128];
    int t = threadIdx.x;
    int s = (t < SCAN_NB) ? g_bsum[t] : 0;
    sh[t] = s;
    __syncthreads();
    #pragma unroll
    for (int off = 1; off < 128; off <<= 1) {
        int add = (t >= off) ? sh[t - off] : 0;
        __syncthreads();
        sh[t] += add;
        __syncthreads();
    }
    if (t < SCAN_NB) g_boff[t] = sh[t] - s;
}

// scan3 + dinv fused
__global__ __launch_bounds__(256) void k_scan3() {
    int boff = g_boff[blockIdx.x];
    int base = blockIdx.x * 1024 + threadIdx.x * 4;
    #pragma unroll
    for (int i = 0; i < 4; i++) {
        int idx = base + i;
        if (idx < N_NODES) {
            int o = g_off[idx] + boff;
            g_off[idx] = o;
            g_cur[idx] = o;
            g_dinv[idx] = rsqrtf((float)(g_cnt[idx] + 1));
        }
    }
}

__global__ void k_bin(const int* __restrict__ ei) {
    int e = blockIdx.x * blockDim.x + threadIdx.x;
    if (e >= N_EDGES) return;
    int src = ei[e];
    int dst = ei[N_EDGES + e];
    int pos = atomicAdd(&g_cur[dst], 1);
    g_srcbin[pos] = src;
}

// ---------------------------------------------------------------------------
// GEMM1 (HMMA): g_h16 = fp16((x @ Wc) * dinv[row])
// ---------------------------------------------------------------------------
__global__ __launch_bounds__(256) void k_gemm1_mma(const float* __restrict__ x) {
    int tid = threadIdx.x, wid = tid >> 5, lane = tid & 31;
    int rowbase = blockIdx.x * 128 + wid * 16;
    int r0 = rowbase + (lane >> 2);
    int r1 = r0 + 8;
    int kc = (lane & 3) * 2;
    bool v0 = r0 < N_NODES, v1 = r1 < N_NODES;

    float acc[8][4];
    #pragma unroll
    for (int nt = 0; nt < 8; nt++)
        #pragma unroll
        for (int i = 0; i < 4; i++) acc[nt][i] = 0.0f;

    const float2 z2 = make_float2(0.f, 0.f);
    #pragma unroll
    for (int kt = 0; kt < 8; kt++) {
        int k0 = kt * 16 + kc;
        float2 x00 = v0 ? *(const float2*)&x[(size_t)r0 * IN_DIM + k0] : z2;
        float2 x02 = v0 ? *(const float2*)&x[(size_t)r0 * IN_DIM + k0 + 8] : z2;
        float2 x10 = v1 ? *(const float2*)&x[(size_t)r1 * IN_DIM + k0] : z2;
        float2 x12 = v1 ? *(const float2*)&x[(size_t)r1 * IN_DIM + k0 + 8] : z2;
        uint32_t ah0, al0, ah1, al1, ah2, al2, ah3, al3;
        split2(x00.x, x00.y, ah0, al0);
        split2(x10.x, x10.y, ah1, al1);
        split2(x02.x, x02.y, ah2, al2);
        split2(x12.x, x12.y, ah3, al3);
        const uint2* Bh = &g_WcB_hi[kt * 256 + lane];
        const uint2* Bl = &g_WcB_lo[kt * 256 + lane];
        #pragma unroll
        for (int nt = 0; nt < 8; nt++) {
            uint2 bh = Bh[nt * 32];
            uint2 bl = Bl[nt * 32];
            mma16816(acc[nt], ah0, ah1, ah2, ah3, bh.x, bh.y);
            mma16816(acc[nt], ah0, ah1, ah2, ah3, bl.x, bl.y);
            mma16816(acc[nt], al0, al1, al2, al3, bh.x, bh.y);
        }
    }

    if (v0) {
        float dv = g_dinv[r0];
        #pragma unroll
        for (int nt = 0; nt < 8; nt++) {
            int c = nt * 8 + kc;
            __half2 hv = __floats2half2_rn(acc[nt][0] * dv, acc[nt][1] * dv);
            *(__half2*)&g_h16[(size_t)r0 * HID_DIM + c] = hv;
        }
    }
    if (v1) {
        float dv = g_dinv[r1];
        #pragma unroll
        for (int nt = 0; nt < 8; nt++) {
            int c = nt * 8 + kc;
            __half2 hv = __floats2half2_rn(acc[nt][2] * dv, acc[nt][3] * dv);
            *(__half2*)&g_h16[(size_t)r1 * HID_DIM + c] = hv;
        }
    }
}

// ---------------------------------------------------------------------------
// CSR aggregate (atomic-free, fp16 gather):
// agg[n] = (sum_{src in in(n)} h16[src] + h16[n]) * dinv[n]
// Block 256 = 32 nodes x 8 threads; thread owns 8 of 64 cols (uint4 = 8 halves).
// ---------------------------------------------------------------------------
__global__ __launch_bounds__(256) void k_aggregate() {
    int tid = threadIdx.x;
    int node = blockIdx.x * 32 + (tid >> 3);
    int sub = tid & 7;
    if (node >= N_NODES) return;
    unsigned gmask = 0xffu << ((tid & 31) & ~7);  // own 8-thread group

    int beg = g_off[node];
    int end = beg + g_cnt[node];

    float acc[8];
    {   // self-loop term
        uint4 hv = *(const uint4*)&g_h16[(size_t)node * HID_DIM + sub * 8];
        const __half2* hp = (const __half2*)&hv;
        #pragma unroll
        for (int q = 0; q < 4; q++) {
            float2 f = __half22float2(hp[q]);
            acc[q * 2] = f.x; acc[q * 2 + 1] = f.y;
        }
    }

    for (int p = beg; p < end; p += 8) {
        int mye = p + sub;
        int mysrc = (mye < end) ? g_srcbin[mye] : 0;
        int m = end - p;  // >= 1
        #pragma unroll
        for (int j = 0; j < 8; j++) {
            if (j < m) {
                int s = __shfl_sync(gmask, mysrc, j, 8);
                uint4 hv = *(const uint4*)&g_h16[(size_t)s * HID_DIM + sub * 8];
                const __half2* hp = (const __half2*)&hv;
                #pragma unroll
                for (int q = 0; q < 4; q++) {
                    float2 f = __half22float2(hp[q]);
                    acc[q * 2] += f.x; acc[q * 2 + 1] += f.y;
                }
            }
        }
    }

    float dv = g_dinv[node];
    float4 o0 = make_float4(acc[0] * dv, acc[1] * dv, acc[2] * dv, acc[3] * dv);
    float4 o1 = make_float4(acc[4] * dv, acc[5] * dv, acc[6] * dv, acc[7] * dv);
    float4* op = (float4*)&g_agg[(size_t)node * HID_DIM + sub * 8];
    op[0] = o0;
    op[1] = o1;
}

// ---------------------------------------------------------------------------
// GEMM2 (HMMA): out = relu(agg + bc) @ Wl + bl
// ---------------------------------------------------------------------------
__global__ __launch_bounds__(256) void k_gemm2_mma(const float* __restrict__ bc,
                                                   const float* __restrict__ bl,
                                                   float* __restrict__ out) {
    int tid = threadIdx.x, wid = tid >> 5, lane = tid & 31;
    int rowbase = blockIdx.x * 128 + wid * 16;
    int r0 = rowbase + (lane >> 2);
    int r1 = r0 + 8;
    int kc = (lane & 3) * 2;
    bool v0 = r0 < N_NODES, v1 = r1 < N_NODES;

    float acc[16][4];
    #pragma unroll
    for (int nt = 0; nt < 16; nt++)
        #pragma unroll
        for (int i = 0; i < 4; i++) acc[nt][i] = 0.0f;

    const float2 z2 = make_float2(0.f, 0.f);
    #pragma unroll
    for (int kt = 0; kt < 4; kt++) {
        int k0 = kt * 16 + kc;
        float2 bca = *(const float2*)&bc[k0];
        float2 bcb = *(const float2*)&bc[k0 + 8];
        float2 a00 = v0 ? *(const float2*)&g_agg[(size_t)r0 * HID_DIM + k0] : z2;
        float2 a02 = v0 ? *(const float2*)&g_agg[(size_t)r0 * HID_DIM + k0 + 8] : z2;
        float2 a10 = v1 ? *(const float2*)&g_agg[(size_t)r1 * HID_DIM + k0] : z2;
        float2 a12 = v1 ? *(const float2*)&g_agg[(size_t)r1 * HID_DIM + k0 + 8] : z2;
        a00.x = fmaxf(a00.x + bca.x, 0.f); a00.y = fmaxf(a00.y + bca.y, 0.f);
        a02.x = fmaxf(a02.x + bcb.x, 0.f); a02.y = fmaxf(a02.y + bcb.y, 0.f);
        a10.x = fmaxf(a10.x + bca.x, 0.f); a10.y = fmaxf(a10.y + bca.y, 0.f);
        a12.x = fmaxf(a12.x + bcb.x, 0.f); a12.y = fmaxf(a12.y + bcb.y, 0.f);
        if (!v0) { a00 = z2; a02 = z2; }
        if (!v1) { a10 = z2; a12 = z2; }
        uint32_t ah0, al0, ah1, al1, ah2, al2, ah3, al3;
        split2(a00.x, a00.y, ah0, al0);
        split2(a10.x, a10.y, ah1, al1);
        split2(a02.x, a02.y, ah2, al2);
        split2(a12.x, a12.y, ah3, al3);
        const uint2* Bh = &g_WlB_hi[kt * 512 + lane];
        const uint2* Bl = &g_WlB_lo[kt * 512 + lane];
        #pragma unroll
        for (int nt = 0; nt < 16; nt++) {
            uint2 bh = Bh[nt * 32];
            uint2 blf = Bl[nt * 32];
            mma16816(acc[nt], ah0, ah1, ah2, ah3, bh.x, bh.y);
            mma16816(acc[nt], ah0, ah1, ah2, ah3, blf.x, blf.y);
            mma16816(acc[nt], al0, al1, al2, al3, bh.x, bh.y);
        }
    }

    if (v0) {
        #pragma unroll
        for (int nt = 0; nt < 16; nt++) {
            int c = nt * 8 + kc;
            float2 b = *(const float2*)&bl[c];
            *(float2*)&out[(size_t)r0 * OUT_DIM + c] =
                make_float2(acc[nt][0] + b.x, acc[nt][1] + b.y);
        }
    }
    if (v1) {
        #pragma unroll
        for (int nt = 0; nt < 16; nt++) {
            int c = nt * 8 + kc;
            float2 b = *(const float2*)&bl[c];
            *(float2*)&out[(size_t)r1 * OUT_DIM + c] =
                make_float2(acc[nt][2] + b.x, acc[nt][3] + b.y);
        }
    }
}

// ---------------------------------------------------------------------------
// Launch
// ---------------------------------------------------------------------------
extern "C" void kernel_launch(void* const* d_in, const int* in_sizes, int n_in,
                              void* d_out, int out_size) {
    const float* x  = (const float*)d_in[0];
    const int*   ei = (const int*)d_in[1];
    const float* Wc = (const float*)d_in[2];
    const float* bc = (const float*)d_in[3];
    const float* Wl = (const float*)d_in[4];
    const float* bl = (const float*)d_in[5];
    float* out = (float*)d_out;

    k_init<<<(N_NODES + 255) / 256, 256>>>(Wc, Wl);
    k_count<<<(N_EDGES + 255) / 256, 256>>>(ei + N_EDGES);
    k_scan1<<<SCAN_NB, 256>>>();
    k_scan2<<<1, 128>>>();
    k_scan3<<<SCAN_NB, 256>>>();
    k_bin<<<(N_EDGES + 255) / 256, 256>>>(ei);

    int grid = (N_NODES + 127) / 128;  // 782
    k_gemm1_mma<<<grid, 256>>>(x);
    k_aggregate<<<(N_NODES + 31) / 32, 256>>>();
    k_gemm2_mma<<<grid, 256>>>(bc, bl, out);
}

// round 7
// speedup vs baseline: 2.6401x; 1.0974x over previous
#include <cuda_runtime.h>
#include <cuda_bf16.h>
#include <cuda_fp16.h>
#include <cstdint>

#define N_NODES 100000
#define N_EDGES 1600000
#define IN_DIM 128
#define HID_DIM 64
#define OUT_DIM 128

#define SCAN_NB 98  // ceil(100000/1024)

// ---------------------------------------------------------------------------
// Device scratch (no allocations allowed)
// ---------------------------------------------------------------------------
__device__ __half g_h16[N_NODES * HID_DIM];   // h_scaled = (x@Wc)*dinv, fp16
__device__ __half g_agg16[N_NODES * HID_DIM]; // relu(agg*dinv + bc), fp16
__device__ float  g_dinv[N_NODES];
__device__ int    g_cnt[N_NODES];             // in-degree (no self-loop)
__device__ int    g_off[N_NODES];             // CSR row start
__device__ int    g_cur[N_NODES];             // binning cursor
__device__ int    g_bsum[SCAN_NB];
__device__ int    g_boff[SCAN_NB];
__device__ int    g_srcbin[N_EDGES];          // CSR: src per in-edge, by dst

// Prepacked B fragments for mma.sync m16n8k16.
// GEMM1: bf16 hi/lo (Wc). GEMM2: fp16 hi/lo (Wl).
__device__ uint2 g_WcB_hi[8 * 8 * 32];
__device__ uint2 g_WcB_lo[8 * 8 * 32];
__device__ uint2 g_WlB_hi[4 * 16 * 32];
__device__ uint2 g_WlB_lo[4 * 16 * 32];

// ---------------------------------------------------------------------------
// Helpers
// ---------------------------------------------------------------------------
// Split fp32 pair (a,b) -> hi/lo bf16x2 packs (a low half, b high half).
__device__ __forceinline__ void split2(float a, float b, uint32_t& hi, uint32_t& lo) {
    uint32_t h;
    asm("cvt.rn.bf16x2.f32 %0, %1, %2;" : "=r"(h) : "f"(b), "f"(a));
    float fa = __uint_as_float(h << 16);
    float fb = __uint_as_float(h & 0xffff0000u);
    asm("cvt.rn.bf16x2.f32 %0, %1, %2;" : "=r"(lo) : "f"(b - fb), "f"(a - fa));
    hi = h;
}

// Split fp32 pair (a,b) -> hi/lo fp16x2 packs.
__device__ __forceinline__ void split2h(float a, float b, uint32_t& hi, uint32_t& lo) {
    __half ha = __float2half_rn(a);
    __half hb = __float2half_rn(b);
    __half la = __float2half_rn(a - __half2float(ha));
    __half lb = __float2half_rn(b - __half2float(hb));
    __half2 hpack = __halves2half2(ha, hb);
    __half2 lpack = __halves2half2(la, lb);
    hi = *reinterpret_cast<uint32_t*>(&hpack);
    lo = *reinterpret_cast<uint32_t*>(&lpack);
}

__device__ __forceinline__ void mma_bf16(float* c, uint32_t a0, uint32_t a1,
                                         uint32_t a2, uint32_t a3,
                                         uint32_t b0, uint32_t b1) {
    asm volatile(
        "mma.sync.aligned.m16n8k16.row.col.f32.bf16.bf16.f32 "
        "{%0,%1,%2,%3}, {%4,%5,%6,%7}, {%8,%9}, {%0,%1,%2,%3};"
        : "+f"(c[0]), "+f"(c[1]), "+f"(c[2]), "+f"(c[3])
        : "r"(a0), "r"(a1), "r"(a2), "r"(a3), "r"(b0), "r"(b1));
}

__device__ __forceinline__ void mma_f16(float* c, uint32_t a0, uint32_t a1,
                                        uint32_t a2, uint32_t a3,
                                        uint32_t b0, uint32_t b1) {
    asm volatile(
        "mma.sync.aligned.m16n8k16.row.col.f32.f16.f16.f32 "
        "{%0,%1,%2,%3}, {%4,%5,%6,%7}, {%8,%9}, {%0,%1,%2,%3};"
        : "+f"(c[0]), "+f"(c[1]), "+f"(c[2]), "+f"(c[3])
        : "r"(a0), "r"(a1), "r"(a2), "r"(a3), "r"(b0), "r"(b1));
}

// ---------------------------------------------------------------------------
// Init: zero degree counters + pack weight fragments
// ---------------------------------------------------------------------------
__global__ void k_init(const float* __restrict__ Wc, const float* __restrict__ Wl) {
    int t = blockIdx.x * blockDim.x + threadIdx.x;
    if (t < N_NODES) g_cnt[t] = 0;
    if (t < 2048) {  // Wc (bf16 split): 8 kt x 8 nt x 32 lanes
        int lane = t & 31, nt = (t >> 5) & 7, kt = t >> 8;
        int k0 = kt * 16 + (lane & 3) * 2;
        int n = nt * 8 + (lane >> 2);
        uint2 hi, lo;
        split2(Wc[k0 * HID_DIM + n], Wc[(k0 + 1) * HID_DIM + n], hi.x, lo.x);
        split2(Wc[(k0 + 8) * HID_DIM + n], Wc[(k0 + 9) * HID_DIM + n], hi.y, lo.y);
        g_WcB_hi[t] = hi;
        g_WcB_lo[t] = lo;
    } else if (t < 4096) {  // Wl (fp16 split): 4 kt x 16 nt x 32 lanes
        int u = t - 2048;
        int lane = u & 31, nt = (u >> 5) & 15, kt = u >> 9;
        int k0 = kt * 16 + (lane & 3) * 2;
        int n = nt * 8 + (lane >> 2);
        uint2 hi, lo;
        split2h(Wl[k0 * OUT_DIM + n], Wl[(k0 + 1) * OUT_DIM + n], hi.x, lo.x);
        split2h(Wl[(k0 + 8) * OUT_DIM + n], Wl[(k0 + 9) * OUT_DIM + n], hi.y, lo.y);
        g_WlB_hi[u] = hi;
        g_WlB_lo[u] = lo;
    }
}

__global__ void k_count(const int* __restrict__ dst) {
    int e = blockIdx.x * blockDim.x + threadIdx.x;
    if (e < N_EDGES) atomicAdd(&g_cnt[dst[e]], 1);
}

// ---------------------------------------------------------------------------
// Exclusive scan of g_cnt -> g_off
// ---------------------------------------------------------------------------
__global__ __launch_bounds__(256) void k_scan1() {
    __shared__ int sh[256];
    int t = threadIdx.x;
    int base = blockIdx.x * 1024 + t * 4;
    int v[4];
    #pragma unroll
    for (int i = 0; i < 4; i++)
        v[i] = (base + i < N_NODES) ? g_cnt[base + i] : 0;
    int s = v[0] + v[1] + v[2] + v[3];
    sh[t] = s;
    __syncthreads();
    #pragma unroll
    for (int off = 1; off < 256; off <<= 1) {
        int add = (t >= off) ? sh[t - off] : 0;
        __syncthreads();
        sh[t] += add;
        __syncthreads();
    }
    int run = sh[t] - s;
    #pragma unroll
    for (int i = 0; i < 4; i++) {
        if (base + i < N_NODES) g_off[base + i] = run;
        run += v[i];
    }
    if (t == 255) g_bsum[blockIdx.x] = sh[255];
}

__global__ __launch_bounds__(128) void k_scan2() {
    __shared__ int sh[128];
    int t = threadIdx.x;
    int s = (t < SCAN_NB) ? g_bsum[t] : 0;
    sh[t] = s;
    __syncthreads();
    #pragma unroll
    for (int off = 1; off < 128; off <<= 1) {
        int add = (t >= off) ? sh[t - off] : 0;
        __syncthreads();
        sh[t] += add;
        __syncthreads();
    }
    if (t < SCAN_NB) g_boff[t] = sh[t] - s;
}

__global__ __launch_bounds__(256) void k_scan3() {
    int boff = g_boff[blockIdx.x];
    int base = blockIdx.x * 1024 + threadIdx.x * 4;
    #pragma unroll
    for (int i = 0; i < 4; i++) {
        int idx = base + i;
        if (idx < N_NODES) {
            int o = g_off[idx] + boff;
            g_off[idx] = o;
            g_cur[idx] = o;
            g_dinv[idx] = rsqrtf((float)(g_cnt[idx] + 1));
        }
    }
}

__global__ void k_bin(const int* __restrict__ ei) {
    int e = blockIdx.x * blockDim.x + threadIdx.x;
    if (e >= N_EDGES) return;
    int src = ei[e];
    int dst = ei[N_EDGES + e];
    int pos = atomicAdd(&g_cur[dst], 1);
    g_srcbin[pos] = src;
}

// ---------------------------------------------------------------------------
// GEMM1 (HMMA bf16 3-product): g_h16 = fp16((x @ Wc) * dinv[row])
// ---------------------------------------------------------------------------
__global__ __launch_bounds__(256) void k_gemm1_mma(const float* __restrict__ x) {
    int tid = threadIdx.x, wid = tid >> 5, lane = tid & 31;
    int rowbase = blockIdx.x * 128 + wid * 16;
    int r0 = rowbase + (lane >> 2);
    int r1 = r0 + 8;
    int kc = (lane & 3) * 2;
    bool v0 = r0 < N_NODES, v1 = r1 < N_NODES;

    float acc[8][4];
    #pragma unroll
    for (int nt = 0; nt < 8; nt++)
        #pragma unroll
        for (int i = 0; i < 4; i++) acc[nt][i] = 0.0f;

    const float2 z2 = make_float2(0.f, 0.f);
    #pragma unroll
    for (int kt = 0; kt < 8; kt++) {
        int k0 = kt * 16 + kc;
        float2 x00 = v0 ? *(const float2*)&x[(size_t)r0 * IN_DIM + k0] : z2;
        float2 x02 = v0 ? *(const float2*)&x[(size_t)r0 * IN_DIM + k0 + 8] : z2;
        float2 x10 = v1 ? *(const float2*)&x[(size_t)r1 * IN_DIM + k0] : z2;
        float2 x12 = v1 ? *(const float2*)&x[(size_t)r1 * IN_DIM + k0 + 8] : z2;
        uint32_t ah0, al0, ah1, al1, ah2, al2, ah3, al3;
        split2(x00.x, x00.y, ah0, al0);
        split2(x10.x, x10.y, ah1, al1);
        split2(x02.x, x02.y, ah2, al2);
        split2(x12.x, x12.y, ah3, al3);
        const uint2* Bh = &g_WcB_hi[kt * 256 + lane];
        const uint2* Bl = &g_WcB_lo[kt * 256 + lane];
        #pragma unroll
        for (int nt = 0; nt < 8; nt++) {
            uint2 bh = Bh[nt * 32];
            uint2 bl = Bl[nt * 32];
            mma_bf16(acc[nt], ah0, ah1, ah2, ah3, bh.x, bh.y);
            mma_bf16(acc[nt], ah0, ah1, ah2, ah3, bl.x, bl.y);
            mma_bf16(acc[nt], al0, al1, al2, al3, bh.x, bh.y);
        }
    }

    if (v0) {
        float dv = g_dinv[r0];
        #pragma unroll
        for (int nt = 0; nt < 8; nt++) {
            int c = nt * 8 + kc;
            __half2 hv = __floats2half2_rn(acc[nt][0] * dv, acc[nt][1] * dv);
            *(__half2*)&g_h16[(size_t)r0 * HID_DIM + c] = hv;
        }
    }
    if (v1) {
        float dv = g_dinv[r1];
        #pragma unroll
        for (int nt = 0; nt < 8; nt++) {
            int c = nt * 8 + kc;
            __half2 hv = __floats2half2_rn(acc[nt][2] * dv, acc[nt][3] * dv);
            *(__half2*)&g_h16[(size_t)r1 * HID_DIM + c] = hv;
        }
    }
}

// ---------------------------------------------------------------------------
// CSR aggregate (atomic-free, fp16 gather) + fused bias/relu:
// agg16[n] = fp16(relu((sum_{src} h16[src] + h16[n]) * dinv[n] + bc))
// Block 256 = 32 nodes x 8 threads; thread owns 8 of 64 cols.
// ---------------------------------------------------------------------------
__global__ __launch_bounds__(256) void k_aggregate(const float* __restrict__ bc) {
    int tid = threadIdx.x;
    int node = blockIdx.x * 32 + (tid >> 3);
    int sub = tid & 7;
    if (node >= N_NODES) return;
    unsigned gmask = 0xffu << ((tid & 31) & ~7);  // own 8-thread group

    int beg = g_off[node];
    int end = beg + g_cnt[node];

    float acc[8];
    {   // self-loop term
        uint4 hv = *(const uint4*)&g_h16[(size_t)node * HID_DIM + sub * 8];
        const __half2* hp = (const __half2*)&hv;
        #pragma unroll
        for (int q = 0; q < 4; q++) {
            float2 f = __half22float2(hp[q]);
            acc[q * 2] = f.x; acc[q * 2 + 1] = f.y;
        }
    }

    for (int p = beg; p < end; p += 8) {
        int mye = p + sub;
        int mysrc = (mye < end) ? g_srcbin[mye] : 0;
        int m = end - p;  // >= 1
        #pragma unroll
        for (int j = 0; j < 8; j++) {
            if (j < m) {
                int s = __shfl_sync(gmask, mysrc, j, 8);
                uint4 hv = *(const uint4*)&g_h16[(size_t)s * HID_DIM + sub * 8];
                const __half2* hp = (const __half2*)&hv;
                #pragma unroll
                for (int q = 0; q < 4; q++) {
                    float2 f = __half22float2(hp[q]);
                    acc[q * 2] += f.x; acc[q * 2 + 1] += f.y;
                }
            }
        }
    }

    float dv = g_dinv[node];
    float4 b0 = *(const float4*)&bc[sub * 8];
    float4 b1 = *(const float4*)&bc[sub * 8 + 4];
    float r[8];
    r[0] = fmaxf(acc[0] * dv + b0.x, 0.f);
    r[1] = fmaxf(acc[1] * dv + b0.y, 0.f);
    r[2] = fmaxf(acc[2] * dv + b0.z, 0.f);
    r[3] = fmaxf(acc[3] * dv + b0.w, 0.f);
    r[4] = fmaxf(acc[4] * dv + b1.x, 0.f);
    r[5] = fmaxf(acc[5] * dv + b1.y, 0.f);
    r[6] = fmaxf(acc[6] * dv + b1.z, 0.f);
    r[7] = fmaxf(acc[7] * dv + b1.w, 0.f);
    uint4 ov;
    __half2 p0 = __floats2half2_rn(r[0], r[1]);
    __half2 p1 = __floats2half2_rn(r[2], r[3]);
    __half2 p2 = __floats2half2_rn(r[4], r[5]);
    __half2 p3 = __floats2half2_rn(r[6], r[7]);
    ov.x = *reinterpret_cast<uint32_t*>(&p0);
    ov.y = *reinterpret_cast<uint32_t*>(&p1);
    ov.z = *reinterpret_cast<uint32_t*>(&p2);
    ov.w = *reinterpret_cast<uint32_t*>(&p3);
    *(uint4*)&g_agg16[(size_t)node * HID_DIM + sub * 8] = ov;
}

// ---------------------------------------------------------------------------
// GEMM2 (HMMA f16 2-product): out = agg16 @ Wl + bl
// A-fragments are direct 4B loads from g_agg16 (relu+bc already applied).
// ---------------------------------------------------------------------------
__global__ __launch_bounds__(256) void k_gemm2_mma(const float* __restrict__ bl,
                                                   float* __restrict__ out) {
    int tid = threadIdx.x, wid = tid >> 5, lane = tid & 31;
    int rowbase = blockIdx.x * 128 + wid * 16;
    int r0 = rowbase + (lane >> 2);
    int r1 = r0 + 8;
    int kc = (lane & 3) * 2;
    bool v0 = r0 < N_NODES, v1 = r1 < N_NODES;

    float acc[16][4];
    #pragma unroll
    for (int nt = 0; nt < 16; nt++)
        #pragma unroll
        for (int i = 0; i < 4; i++) acc[nt][i] = 0.0f;

    #pragma unroll
    for (int kt = 0; kt < 4; kt++) {
        int k0 = kt * 16 + kc;
        uint32_t a0 = 0, a1 = 0, a2 = 0, a3 = 0;
        if (v0) {
            a0 = *(const uint32_t*)&g_agg16[(size_t)r0 * HID_DIM + k0];
            a2 = *(const uint32_t*)&g_agg16[(size_t)r0 * HID_DIM + k0 + 8];
        }
        if (v1) {
            a1 = *(const uint32_t*)&g_agg16[(size_t)r1 * HID_DIM + k0];
            a3 = *(const uint32_t*)&g_agg16[(size_t)r1 * HID_DIM + k0 + 8];
        }
        const uint2* Bh = &g_WlB_hi[kt * 512 + lane];
        const uint2* Bl = &g_WlB_lo[kt * 512 + lane];
        #pragma unroll
        for (int nt = 0; nt < 16; nt++) {
            uint2 bh = Bh[nt * 32];
            uint2 blf = Bl[nt * 32];
            mma_f16(acc[nt], a0, a1, a2, a3, bh.x, bh.y);
            mma_f16(acc[nt], a0, a1, a2, a3, blf.x, blf.y);
        }
    }

    if (v0) {
        #pragma unroll
        for (int nt = 0; nt < 16; nt++) {
            int c = nt * 8 + kc;
            float2 b = *(const float2*)&bl[c];
            *(float2*)&out[(size_t)r0 * OUT_DIM + c] =
                make_float2(acc[nt][0] + b.x, acc[nt][1] + b.y);
        }
    }
    if (v1) {
        #pragma unroll
        for (int nt = 0; nt < 16; nt++) {
            int c = nt * 8 + kc;
            float2 b = *(const float2*)&bl[c];
            *(float2*)&out[(size_t)r1 * OUT_DIM + c] =
                make_float2(acc[nt][2] + b.x, acc[nt][3] + b.y);
        }
    }
}

// ---------------------------------------------------------------------------
// Launch
// ---------------------------------------------------------------------------
extern "C" void kernel_launch(void* const* d_in, const int* in_sizes, int n_in,
                              void* d_out, int out_size) {
    const float* x  = (const float*)d_in[0];
    const int*   ei = (const int*)d_in[1];
    const float* Wc = (const float*)d_in[2];
    const float* bc = (const float*)d_in[3];
    const float* Wl = (const float*)d_in[4];
    const float* bl = (const float*)d_in[5];
    float* out = (float*)d_out;

    k_init<<<(N_NODES + 255) / 256, 256>>>(Wc, Wl);
    k_count<<<(N_EDGES + 255) / 256, 256>>>(ei + N_EDGES);
    k_scan1<<<SCAN_NB, 256>>>();
    k_scan2<<<1, 128>>>();
    k_scan3<<<SCAN_NB, 256>>>();
    k_bin<<<(N_EDGES + 255) / 256, 256>>>(ei);

    int grid = (N_NODES + 127) / 128;  // 782
    k_gemm1_mma<<<grid, 256>>>(x);
    k_aggregate<<<(N_NODES + 31) / 32, 256>>>(bc);
    k_gemm2_mma<<<grid, 256>>>(bl, out);
}

// round 8
// speedup vs baseline: 2.7285x; 1.0335x over previous
#include <cuda_runtime.h>
#include <cuda_bf16.h>
#include <cuda_fp16.h>
#include <cstdint>

#define N_NODES 100000
#define N_EDGES 1600000
#define IN_DIM 128
#define HID_DIM 64
#define OUT_DIM 128

#define SCAN_NB 98  // ceil(100000/1024)
#define SCAN_FLAG (1 << 30)

// ---------------------------------------------------------------------------
// Device scratch (no allocations allowed)
// ---------------------------------------------------------------------------
__device__ __half g_h16[N_NODES * HID_DIM];   // h_scaled = (x@Wc)*dinv, fp16
__device__ __half g_agg16[N_NODES * HID_DIM]; // relu(agg*dinv + bc), fp16
__device__ float  g_dinv[N_NODES];
__device__ int    g_cnt[N_NODES];             // in-degree (no self-loop)
__device__ int    g_off[N_NODES];             // CSR row start
__device__ int    g_cur[N_NODES];             // binning cursor
__device__ int    g_bsum[SCAN_NB];            // lookback aggregates (flag bit 30)
__device__ int    g_srcbin[N_EDGES];          // CSR: src per in-edge, by dst

// Prepacked B fragments for mma.sync m16n8k16.
// GEMM1: bf16 hi/lo (Wc). GEMM2: fp16 hi/lo (Wl).
__device__ uint2 g_WcB_hi[8 * 8 * 32];
__device__ uint2 g_WcB_lo[8 * 8 * 32];
__device__ uint2 g_WlB_hi[4 * 16 * 32];
__device__ uint2 g_WlB_lo[4 * 16 * 32];

// ---------------------------------------------------------------------------
// Helpers
// ---------------------------------------------------------------------------
// Split fp32 pair (a,b) -> hi/lo bf16x2 packs (a low half, b high half).
__device__ __forceinline__ void split2(float a, float b, uint32_t& hi, uint32_t& lo) {
    uint32_t h;
    asm("cvt.rn.bf16x2.f32 %0, %1, %2;" : "=r"(h) : "f"(b), "f"(a));
    float fa = __uint_as_float(h << 16);
    float fb = __uint_as_float(h & 0xffff0000u);
    asm("cvt.rn.bf16x2.f32 %0, %1, %2;" : "=r"(lo) : "f"(b - fb), "f"(a - fa));
    hi = h;
}

// Split fp32 pair (a,b) -> hi/lo fp16x2 packs.
__device__ __forceinline__ void split2h(float a, float b, uint32_t& hi, uint32_t& lo) {
    __half ha = __float2half_rn(a);
    __half hb = __float2half_rn(b);
    __half la = __float2half_rn(a - __half2float(ha));
    __half lb = __float2half_rn(b - __half2float(hb));
    __half2 hpack = __halves2half2(ha, hb);
    __half2 lpack = __halves2half2(la, lb);
    hi = *reinterpret_cast<uint32_t*>(&hpack);
    lo = *reinterpret_cast<uint32_t*>(&lpack);
}

__device__ __forceinline__ void mma_bf16(float* c, uint32_t a0, uint32_t a1,
                                         uint32_t a2, uint32_t a3,
                                         uint32_t b0, uint32_t b1) {
    asm volatile(
        "mma.sync.aligned.m16n8k16.row.col.f32.bf16.bf16.f32 "
        "{%0,%1,%2,%3}, {%4,%5,%6,%7}, {%8,%9}, {%0,%1,%2,%3};"
        : "+f"(c[0]), "+f"(c[1]), "+f"(c[2]), "+f"(c[3])
        : "r"(a0), "r"(a1), "r"(a2), "r"(a3), "r"(b0), "r"(b1));
}

__device__ __forceinline__ void mma_f16(float* c, uint32_t a0, uint32_t a1,
                                        uint32_t a2, uint32_t a3,
                                        uint32_t b0, uint32_t b1) {
    asm volatile(
        "mma.sync.aligned.m16n8k16.row.col.f32.f16.f16.f32 "
        "{%0,%1,%2,%3}, {%4,%5,%6,%7}, {%8,%9}, {%0,%1,%2,%3};"
        : "+f"(c[0]), "+f"(c[1]), "+f"(c[2]), "+f"(c[3])
        : "r"(a0), "r"(a1), "r"(a2), "r"(a3), "r"(b0), "r"(b1));
}

// ---------------------------------------------------------------------------
// Init: zero counters/lookback state + pack weight fragments
// ---------------------------------------------------------------------------
__global__ void k_init(const float* __restrict__ Wc, const float* __restrict__ Wl) {
    int t = blockIdx.x * blockDim.x + threadIdx.x;
    if (t < N_NODES) g_cnt[t] = 0;
    if (t < SCAN_NB) g_bsum[t] = 0;  // flag bit clear
    if (t < 2048) {  // Wc (bf16 split): 8 kt x 8 nt x 32 lanes
        int lane = t & 31, nt = (t >> 5) & 7, kt = t >> 8;
        int k0 = kt * 16 + (lane & 3) * 2;
        int n = nt * 8 + (lane >> 2);
        uint2 hi, lo;
        split2(Wc[k0 * HID_DIM + n], Wc[(k0 + 1) * HID_DIM + n], hi.x, lo.x);
        split2(Wc[(k0 + 8) * HID_DIM + n], Wc[(k0 + 9) * HID_DIM + n], hi.y, lo.y);
        g_WcB_hi[t] = hi;
        g_WcB_lo[t] = lo;
    } else if (t < 4096) {  // Wl (fp16 split): 4 kt x 16 nt x 32 lanes
        int u = t - 2048;
        int lane = u & 31, nt = (u >> 5) & 15, kt = u >> 9;
        int k0 = kt * 16 + (lane & 3) * 2;
        int n = nt * 8 + (lane >> 2);
        uint2 hi, lo;
        split2h(Wl[k0 * OUT_DIM + n], Wl[(k0 + 1) * OUT_DIM + n], hi.x, lo.x);
        split2h(Wl[(k0 + 8) * OUT_DIM + n], Wl[(k0 + 9) * OUT_DIM + n], hi.y, lo.y);
        g_WlB_hi[u] = hi;
        g_WlB_lo[u] = lo;
    }
}

// Count in-degrees, 4 edges per thread.
__global__ void k_count(const int* __restrict__ dst) {
    int e4 = blockIdx.x * blockDim.x + threadIdx.x;
    if (e4 >= N_EDGES / 4) return;
    int4 d = ((const int4*)dst)[e4];
    atomicAdd(&g_cnt[d.x], 1);
    atomicAdd(&g_cnt[d.y], 1);
    atomicAdd(&g_cnt[d.z], 1);
    atomicAdd(&g_cnt[d.w], 1);
}

// ---------------------------------------------------------------------------
// Fused exclusive scan (decoupled lookback, one kernel) + dinv + cursor init.
// 98 blocks x 256 threads, 1024 nodes per block; all blocks fit in one wave.
// ---------------------------------------------------------------------------
__global__ __launch_bounds__(256) void k_scan_fused() {
    __shared__ int sh[256];
    int t = threadIdx.x, b = blockIdx.x;
    int base = b * 1024 + t * 4;
    int v[4];
    #pragma unroll
    for (int i = 0; i < 4; i++)
        v[i] = (base + i < N_NODES) ? g_cnt[base + i] : 0;
    int s = v[0] + v[1] + v[2] + v[3];
    sh[t] = s;
    __syncthreads();
    #pragma unroll
    for (int off = 1; off < 256; off <<= 1) {
        int add = (t >= off) ? sh[t - off] : 0;
        __syncthreads();
        sh[t] += add;
        __syncthreads();
    }
    // Publish this block's total ASAP (value | flag in one word).
    if (t == 255) atomicExch(&g_bsum[b], sh[255] | SCAN_FLAG);
    int ex = sh[t] - s;  // exclusive prefix within block

    // Lookback: thread t reads predecessor t's aggregate (b <= 97 < 256).
    int part = 0;
    if (t < b) {
        int val;
        do { val = atomicAdd(&g_bsum[t], 0); } while (!(val & SCAN_FLAG));
        part = val & ~SCAN_FLAG;
    }
    __syncthreads();  // everyone done with scan values in sh
    sh[t] = part;
    __syncthreads();
    #pragma unroll
    for (int off = 128; off >= 1; off >>= 1) {
        if (t < off) sh[t] += sh[t + off];
        __syncthreads();
    }
    int boff = sh[0];

    int run = ex + boff;
    #pragma unroll
    for (int i = 0; i < 4; i++) {
        int idx = base + i;
        if (idx < N_NODES) {
            g_off[idx] = run;
            g_cur[idx] = run;
            g_dinv[idx] = rsqrtf((float)(v[i] + 1));
            run += v[i];
        }
    }
}

// Bin edges by dst, 4 edges per thread.
__global__ void k_bin(const int* __restrict__ ei) {
    int e4 = blockIdx.x * blockDim.x + threadIdx.x;
    if (e4 >= N_EDGES / 4) return;
    int4 s = ((const int4*)ei)[e4];
    int4 d = ((const int4*)(ei + N_EDGES))[e4];
    int p0 = atomicAdd(&g_cur[d.x], 1); g_srcbin[p0] = s.x;
    int p1 = atomicAdd(&g_cur[d.y], 1); g_srcbin[p1] = s.y;
    int p2 = atomicAdd(&g_cur[d.z], 1); g_srcbin[p2] = s.z;
    int p3 = atomicAdd(&g_cur[d.w], 1); g_srcbin[p3] = s.w;
}

// ---------------------------------------------------------------------------
// GEMM1 (HMMA bf16 3-product): g_h16 = fp16((x @ Wc) * dinv[row])
// ---------------------------------------------------------------------------
__global__ __launch_bounds__(256) void k_gemm1_mma(const float* __restrict__ x) {
    int tid = threadIdx.x, wid = tid >> 5, lane = tid & 31;
    int rowbase = blockIdx.x * 128 + wid * 16;
    int r0 = rowbase + (lane >> 2);
    int r1 = r0 + 8;
    int kc = (lane & 3) * 2;
    bool v0 = r0 < N_NODES, v1 = r1 < N_NODES;

    float acc[8][4];
    #pragma unroll
    for (int nt = 0; nt < 8; nt++)
        #pragma unroll
        for (int i = 0; i < 4; i++) acc[nt][i] = 0.0f;

    const float2 z2 = make_float2(0.f, 0.f);
    #pragma unroll
    for (int kt = 0; kt < 8; kt++) {
        int k0 = kt * 16 + kc;
        float2 x00 = v0 ? *(const float2*)&x[(size_t)r0 * IN_DIM + k0] : z2;
        float2 x02 = v0 ? *(const float2*)&x[(size_t)r0 * IN_DIM + k0 + 8] : z2;
        float2 x10 = v1 ? *(const float2*)&x[(size_t)r1 * IN_DIM + k0] : z2;
        float2 x12 = v1 ? *(const float2*)&x[(size_t)r1 * IN_DIM + k0 + 8] : z2;
        uint32_t ah0, al0, ah1, al1, ah2, al2, ah3, al3;
        split2(x00.x, x00.y, ah0, al0);
        split2(x10.x, x10.y, ah1, al1);
        split2(x02.x, x02.y, ah2, al2);
        split2(x12.x, x12.y, ah3, al3);
        const uint2* Bh = &g_WcB_hi[kt * 256 + lane];
        const uint2* Bl = &g_WcB_lo[kt * 256 + lane];
        #pragma unroll
        for (int nt = 0; nt < 8; nt++) {
            uint2 bh = Bh[nt * 32];
            uint2 bl = Bl[nt * 32];
            mma_bf16(acc[nt], ah0, ah1, ah2, ah3, bh.x, bh.y);
            mma_bf16(acc[nt], ah0, ah1, ah2, ah3, bl.x, bl.y);
            mma_bf16(acc[nt], al0, al1, al2, al3, bh.x, bh.y);
        }
    }

    if (v0) {
        float dv = g_dinv[r0];
        #pragma unroll
        for (int nt = 0; nt < 8; nt++) {
            int c = nt * 8 + kc;
            __half2 hv = __floats2half2_rn(acc[nt][0] * dv, acc[nt][1] * dv);
            *(__half2*)&g_h16[(size_t)r0 * HID_DIM + c] = hv;
        }
    }
    if (v1) {
        float dv = g_dinv[r1];
        #pragma unroll
        for (int nt = 0; nt < 8; nt++) {
            int c = nt * 8 + kc;
            __half2 hv = __floats2half2_rn(acc[nt][2] * dv, acc[nt][3] * dv);
            *(__half2*)&g_h16[(size_t)r1 * HID_DIM + c] = hv;
        }
    }
}

// ---------------------------------------------------------------------------
// CSR aggregate (atomic-free, fp16 gather) + fused bias/relu:
// agg16[n] = fp16(relu((sum_{src} h16[src] + h16[n]) * dinv[n] + bc))
// Block 256 = 32 nodes x 8 threads; thread owns 8 of 64 cols.
// Full 8-edge batches unguarded; remainder handled once.
// ---------------------------------------------------------------------------
__global__ __launch_bounds__(256) void k_aggregate(const float* __restrict__ bc) {
    int tid = threadIdx.x;
    int node = blockIdx.x * 32 + (tid >> 3);
    int sub = tid & 7;
    if (node >= N_NODES) return;
    unsigned gmask = 0xffu << ((tid & 31) & ~7);  // own 8-thread group

    int beg = g_off[node];
    int cnt = g_cnt[node];
    int end = beg + cnt;

    float acc[8];
    {   // self-loop term
        uint4 hv = *(const uint4*)&g_h16[(size_t)node * HID_DIM + sub * 8];
        const __half2* hp = (const __half2*)&hv;
        #pragma unroll
        for (int q = 0; q < 4; q++) {
            float2 f = __half22float2(hp[q]);
            acc[q * 2] = f.x; acc[q * 2 + 1] = f.y;
        }
    }

    int p = beg;
    int full_end = beg + (cnt & ~7);
    for (; p < full_end; p += 8) {
        int mysrc = g_srcbin[p + sub];
        #pragma unroll
        for (int j = 0; j < 8; j++) {
            int s = __shfl_sync(gmask, mysrc, j, 8);
            uint4 hv = *(const uint4*)&g_h16[(size_t)s * HID_DIM + sub * 8];
            const __half2* hp = (const __half2*)&hv;
            #pragma unroll
            for (int q = 0; q < 4; q++) {
                float2 f = __half22float2(hp[q]);
                acc[q * 2] += f.x; acc[q * 2 + 1] += f.y;
            }
        }
    }
    if (p < end) {
        int mye = p + sub;
        int mysrc = (mye < end) ? g_srcbin[mye] : 0;
        int m = end - p;
        #pragma unroll
        for (int j = 0; j < 8; j++) {
            if (j < m) {
                int s = __shfl_sync(gmask, mysrc, j, 8);
                uint4 hv = *(const uint4*)&g_h16[(size_t)s * HID_DIM + sub * 8];
                const __half2* hp = (const __half2*)&hv;
                #pragma unroll
                for (int q = 0; q < 4; q++) {
                    float2 f = __half22float2(hp[q]);
                    acc[q * 2] += f.x; acc[q * 2 + 1] += f.y;
                }
            }
        }
    }

    float dv = g_dinv[node];
    float4 b0 = *(const float4*)&bc[sub * 8];
    float4 b1 = *(const float4*)&bc[sub * 8 + 4];
    float r[8];
    r[0] = fmaxf(acc[0] * dv + b0.x, 0.f);
    r[1] = fmaxf(acc[1] * dv + b0.y, 0.f);
    r[2] = fmaxf(acc[2] * dv + b0.z, 0.f);
    r[3] = fmaxf(acc[3] * dv + b0.w, 0.f);
    r[4] = fmaxf(acc[4] * dv + b1.x, 0.f);
    r[5] = fmaxf(acc[5] * dv + b1.y, 0.f);
    r[6] = fmaxf(acc[6] * dv + b1.z, 0.f);
    r[7] = fmaxf(acc[7] * dv + b1.w, 0.f);
    uint4 ov;
    __half2 p0 = __floats2half2_rn(r[0], r[1]);
    __half2 p1 = __floats2half2_rn(r[2], r[3]);
    __half2 p2 = __floats2half2_rn(r[4], r[5]);
    __half2 p3 = __floats2half2_rn(r[6], r[7]);
    ov.x = *reinterpret_cast<uint32_t*>(&p0);
    ov.y = *reinterpret_cast<uint32_t*>(&p1);
    ov.z = *reinterpret_cast<uint32_t*>(&p2);
    ov.w = *reinterpret_cast<uint32_t*>(&p3);
    *(uint4*)&g_agg16[(size_t)node * HID_DIM + sub * 8] = ov;
}

// ---------------------------------------------------------------------------
// GEMM2 (HMMA f16 2-product): out = agg16 @ Wl + bl
// ---------------------------------------------------------------------------
__global__ __launch_bounds__(256) void k_gemm2_mma(const float* __restrict__ bl,
                                                   float* __restrict__ out) {
    int tid = threadIdx.x, wid = tid >> 5, lane = tid & 31;
    int rowbase = blockIdx.x * 128 + wid * 16;
    int r0 = rowbase + (lane >> 2);
    int r1 = r0 + 8;
    int kc = (lane & 3) * 2;
    bool v0 = r0 < N_NODES, v1 = r1 < N_NODES;

    float acc[16][4];
    #pragma unroll
    for (int nt = 0; nt < 16; nt++)
        #pragma unroll
        for (int i = 0; i < 4; i++) acc[nt][i] = 0.0f;

    #pragma unroll
    for (int kt = 0; kt < 4; kt++) {
        int k0 = kt * 16 + kc;
        uint32_t a0 = 0, a1 = 0, a2 = 0, a3 = 0;
        if (v0) {
            a0 = *(const uint32_t*)&g_agg16[(size_t)r0 * HID_DIM + k0];
            a2 = *(const uint32_t*)&g_agg16[(size_t)r0 * HID_DIM + k0 + 8];
        }
        if (v1) {
            a1 = *(const uint32_t*)&g_agg16[(size_t)r1 * HID_DIM + k0];
            a3 = *(const uint32_t*)&g_agg16[(size_t)r1 * HID_DIM + k0 + 8];
        }
        const uint2* Bh = &g_WlB_hi[kt * 512 + lane];
        const uint2* Bl = &g_WlB_lo[kt * 512 + lane];
        #pragma unroll
        for (int nt = 0; nt < 16; nt++) {
            uint2 bh = Bh[nt * 32];
            uint2 blf = Bl[nt * 32];
            mma_f16(acc[nt], a0, a1, a2, a3, bh.x, bh.y);
            mma_f16(acc[nt], a0, a1, a2, a3, blf.x, blf.y);
        }
    }

    if (v0) {
        #pragma unroll
        for (int nt = 0; nt < 16; nt++) {
            int c = nt * 8 + kc;
            float2 b = *(const float2*)&bl[c];
            *(float2*)&out[(size_t)r0 * OUT_DIM + c] =
                make_float2(acc[nt][0] + b.x, acc[nt][1] + b.y);
        }
    }
    if (v1) {
        #pragma unroll
        for (int nt = 0; nt < 16; nt++) {
            int c = nt * 8 + kc;
            float2 b = *(const float2*)&bl[c];
            *(float2*)&out[(size_t)r1 * OUT_DIM + c] =
                make_float2(acc[nt][2] + b.x, acc[nt][3] + b.y);
        }
    }
}

// ---------------------------------------------------------------------------
// Launch (7 kernels)
// ---------------------------------------------------------------------------
extern "C" void kernel_launch(void* const* d_in, const int* in_sizes, int n_in,
                              void* d_out, int out_size) {
    const float* x  = (const float*)d_in[0];
    const int*   ei = (const int*)d_in[1];
    const float* Wc = (const float*)d_in[2];
    const float* bc = (const float*)d_in[3];
    const float* Wl = (const float*)d_in[4];
    const float* bl = (const float*)d_in[5];
    float* out = (float*)d_out;

    k_init<<<(N_NODES + 255) / 256, 256>>>(Wc, Wl);
    k_count<<<(N_EDGES / 4 + 255) / 256, 256>>>(ei + N_EDGES);
    k_scan_fused<<<SCAN_NB, 256>>>();
    k_bin<<<(N_EDGES / 4 + 255) / 256, 256>>>(ei);

    int grid = (N_NODES + 127) / 128;  // 782
    k_gemm1_mma<<<grid, 256>>>(x);
    k_aggregate<<<(N_NODES + 31) / 32, 256>>>(bc);
    k_gemm2_mma<<<grid, 256>>>(bl, out);
}

// round 9
// speedup vs baseline: 2.8600x; 1.0482x over previous
#include <cuda_runtime.h>
#include <cuda_bf16.h>
#include <cuda_fp16.h>
#include <cstdint>

#define N_NODES 100000
#define N_EDGES 1600000
#define IN_DIM 128
#define HID_DIM 64
#define OUT_DIM 128

#define SCAN_NB 98  // ceil(100000/1024)
#define SCAN_FLAG (1 << 30)

// ---------------------------------------------------------------------------
// Device scratch (no allocations allowed)
// ---------------------------------------------------------------------------
__device__ __half g_h16[N_NODES * HID_DIM];   // h_scaled = (x@Wc)*dinv, fp16
__device__ __half g_agg16[N_NODES * HID_DIM]; // relu(agg*dinv + bc), fp16
__device__ float  g_dinv[N_NODES];
__device__ int    g_cnt[N_NODES];             // in-degree (no self-loop)
__device__ int    g_off[N_NODES];             // CSR row start
__device__ int    g_slot[N_EDGES];            // per-edge slot within dst row
__device__ int    g_bsum[SCAN_NB];            // lookback aggregates (flag bit 30)
__device__ int    g_srcbin[N_EDGES];          // CSR: src per in-edge, by dst

// Prepacked B fragments for mma.sync m16n8k16 (fp16 hi/lo for both GEMMs).
__device__ uint2 g_WcB_hi[8 * 8 * 32];
__device__ uint2 g_WcB_lo[8 * 8 * 32];
__device__ uint2 g_WlB_hi[4 * 16 * 32];
__device__ uint2 g_WlB_lo[4 * 16 * 32];

// ---------------------------------------------------------------------------
// Helpers
// ---------------------------------------------------------------------------
// Split fp32 pair (a,b) -> hi/lo fp16x2 packs (a low half, b high half).
__device__ __forceinline__ void split2h(float a, float b, uint32_t& hi, uint32_t& lo) {
    __half ha = __float2half_rn(a);
    __half hb = __float2half_rn(b);
    __half la = __float2half_rn(a - __half2float(ha));
    __half lb = __float2half_rn(b - __half2float(hb));
    __half2 hpack = __halves2half2(ha, hb);
    __half2 lpack = __halves2half2(la, lb);
    hi = *reinterpret_cast<uint32_t*>(&hpack);
    lo = *reinterpret_cast<uint32_t*>(&lpack);
}

__device__ __forceinline__ void mma_f16(float* c, uint32_t a0, uint32_t a1,
                                        uint32_t a2, uint32_t a3,
                                        uint32_t b0, uint32_t b1) {
    asm volatile(
        "mma.sync.aligned.m16n8k16.row.col.f32.f16.f16.f32 "
        "{%0,%1,%2,%3}, {%4,%5,%6,%7}, {%8,%9}, {%0,%1,%2,%3};"
        : "+f"(c[0]), "+f"(c[1]), "+f"(c[2]), "+f"(c[3])
        : "r"(a0), "r"(a1), "r"(a2), "r"(a3), "r"(b0), "r"(b1));
}

// ---------------------------------------------------------------------------
// Init: zero counters/lookback state + pack weight fragments (fp16 hi/lo)
// ---------------------------------------------------------------------------
__global__ void k_init(const float* __restrict__ Wc, const float* __restrict__ Wl) {
    int t = blockIdx.x * blockDim.x + threadIdx.x;
    if (t < N_NODES) g_cnt[t] = 0;
    if (t < SCAN_NB) g_bsum[t] = 0;  // flag bit clear
    if (t < 2048) {  // Wc: 8 kt x 8 nt x 32 lanes
        int lane = t & 31, nt = (t >> 5) & 7, kt = t >> 8;
        int k0 = kt * 16 + (lane & 3) * 2;
        int n = nt * 8 + (lane >> 2);
        uint2 hi, lo;
        split2h(Wc[k0 * HID_DIM + n], Wc[(k0 + 1) * HID_DIM + n], hi.x, lo.x);
        split2h(Wc[(k0 + 8) * HID_DIM + n], Wc[(k0 + 9) * HID_DIM + n], hi.y, lo.y);
        g_WcB_hi[t] = hi;
        g_WcB_lo[t] = lo;
    } else if (t < 4096) {  // Wl: 4 kt x 16 nt x 32 lanes
        int u = t - 2048;
        int lane = u & 31, nt = (u >> 5) & 15, kt = u >> 9;
        int k0 = kt * 16 + (lane & 3) * 2;
        int n = nt * 8 + (lane >> 2);
        uint2 hi, lo;
        split2h(Wl[k0 * OUT_DIM + n], Wl[(k0 + 1) * OUT_DIM + n], hi.x, lo.x);
        split2h(Wl[(k0 + 8) * OUT_DIM + n], Wl[(k0 + 9) * OUT_DIM + n], hi.y, lo.y);
        g_WlB_hi[u] = hi;
        g_WlB_lo[u] = lo;
    }
}

// Count in-degrees AND record each edge's slot within its dst row.
__global__ void k_count(const int* __restrict__ dst) {
    int e4 = blockIdx.x * blockDim.x + threadIdx.x;
    if (e4 >= N_EDGES / 4) return;
    int4 d = ((const int4*)dst)[e4];
    int4 s;
    s.x = atomicAdd(&g_cnt[d.x], 1);
    s.y = atomicAdd(&g_cnt[d.y], 1);
    s.z = atomicAdd(&g_cnt[d.z], 1);
    s.w = atomicAdd(&g_cnt[d.w], 1);
    ((int4*)g_slot)[e4] = s;
}

// ---------------------------------------------------------------------------
// Fused exclusive scan (decoupled lookback, one kernel) + dinv.
// 98 blocks x 256 threads, 1024 nodes per block; all blocks fit in one wave.
// ---------------------------------------------------------------------------
__global__ __launch_bounds__(256) void k_scan_fused() {
    __shared__ int sh[256];
    int t = threadIdx.x, b = blockIdx.x;
    int base = b * 1024 + t * 4;
    int v[4];
    #pragma unroll
    for (int i = 0; i < 4; i++)
        v[i] = (base + i < N_NODES) ? g_cnt[base + i] : 0;
    int s = v[0] + v[1] + v[2] + v[3];
    sh[t] = s;
    __syncthreads();
    #pragma unroll
    for (int off = 1; off < 256; off <<= 1) {
        int add = (t >= off) ? sh[t - off] : 0;
        __syncthreads();
        sh[t] += add;
        __syncthreads();
    }
    if (t == 255) atomicExch(&g_bsum[b], sh[255] | SCAN_FLAG);
    int ex = sh[t] - s;  // exclusive prefix within block

    int part = 0;
    if (t < b) {
        int val;
        do { val = atomicAdd(&g_bsum[t], 0); } while (!(val & SCAN_FLAG));
        part = val & ~SCAN_FLAG;
    }
    __syncthreads();
    sh[t] = part;
    __syncthreads();
    #pragma unroll
    for (int off = 128; off >= 1; off >>= 1) {
        if (t < off) sh[t] += sh[t + off];
        __syncthreads();
    }
    int boff = sh[0];

    int run = ex + boff;
    #pragma unroll
    for (int i = 0; i < 4; i++) {
        int idx = base + i;
        if (idx < N_NODES) {
            g_off[idx] = run;
            g_dinv[idx] = rsqrtf((float)(v[i] + 1));
            run += v[i];
        }
    }
}

// Bin edges by dst — atomic-free: pos = off[dst] + slot.
__global__ void k_bin(const int* __restrict__ ei) {
    int e4 = blockIdx.x * blockDim.x + threadIdx.x;
    if (e4 >= N_EDGES / 4) return;
    int4 s = ((const int4*)ei)[e4];
    int4 d = ((const int4*)(ei + N_EDGES))[e4];
    int4 sl = ((const int4*)g_slot)[e4];
    g_srcbin[__ldg(&g_off[d.x]) + sl.x] = s.x;
    g_srcbin[__ldg(&g_off[d.y]) + sl.y] = s.y;
    g_srcbin[__ldg(&g_off[d.z]) + sl.z] = s.z;
    g_srcbin[__ldg(&g_off[d.w]) + sl.w] = s.w;
}

// ---------------------------------------------------------------------------
// GEMM1 (HMMA fp16 2-product): g_h16 = fp16((x @ Wc) * dinv[row])
// acc = xh*Wh_hi + xh*Wl_lo etc: acc = Ah*Bh + Ah*Bl + Al*Bh ~ use 2-product:
// acc = Ah*(Bh) + (Al*Bh + Ah*Bl): with fp16 splits the dominant residuals
// are captured by  Ah*Bl + Al*Bh; Al*Bl ~ 2^-44 negligible.
// We use: acc = Ah*Bh + Ah*Bl + Al*Bh? No — fp16 split residual is 2^-11,
// so Ah*Bl ~ 2^-11, Al*Bh ~ 2^-11, Al*Bl ~ 2^-22 (negligible vs fp32 accum).
// But 2-product form acc = Ah*Bh + (Ah*Bl + Al*Bh) needs 3 MMAs unless we
// pre-add: C = Ah*(Bh+Bl)? Instead use the standard trick: since
// |residual| ~ 2^-11 and products Ah*Bl, Al*Bh each ~2^-11, dropping Al*Bh
// leaves error 2^-11 * |x| per product — too big. So: 2 MMAs as
// acc = Ah*Bh + (Al*Bh + Ah*Bl measured jointly) is impossible; we instead
// run acc = Ah*Bh + Am*Bm where Am = fp16(A - Ah) and Bm packs Bl PLUS we
// fold Ah*Bl by using B operand = Bh for Am and separately relying on
// Ah*Bl: we keep 3 MMAs for correctness... BUT fp16 residuals are 32x
// smaller than bf16's, so we can DROP the Ah*Bl term only if W's lo part
// is folded into... simplest safe choice: keep 3 products (same count as
// bf16) but with fp16's far better accuracy; OR 2 products with Bh_full =
// fp16 pair-sum. We use 3 products (correctness first), fp16 precision.
// ---------------------------------------------------------------------------
__global__ __launch_bounds__(256) void k_gemm1_mma(const float* __restrict__ x) {
    int tid = threadIdx.x, wid = tid >> 5, lane = tid & 31;
    int rowbase = blockIdx.x * 128 + wid * 16;
    int r0 = rowbase + (lane >> 2);
    int r1 = r0 + 8;
    int kc = (lane & 3) * 2;
    bool v0 = r0 < N_NODES, v1 = r1 < N_NODES;

    float acc[8][4];
    #pragma unroll
    for (int nt = 0; nt < 8; nt++)
        #pragma unroll
        for (int i = 0; i < 4; i++) acc[nt][i] = 0.0f;

    const float2 z2 = make_float2(0.f, 0.f);
    #pragma unroll
    for (int kt = 0; kt < 8; kt++) {
        int k0 = kt * 16 + kc;
        float2 x00 = v0 ? *(const float2*)&x[(size_t)r0 * IN_DIM + k0] : z2;
        float2 x02 = v0 ? *(const float2*)&x[(size_t)r0 * IN_DIM + k0 + 8] : z2;
        float2 x10 = v1 ? *(const float2*)&x[(size_t)r1 * IN_DIM + k0] : z2;
        float2 x12 = v1 ? *(const float2*)&x[(size_t)r1 * IN_DIM + k0 + 8] : z2;
        uint32_t ah0, al0, ah1, al1, ah2, al2, ah3, al3;
        split2h(x00.x, x00.y, ah0, al0);
        split2h(x10.x, x10.y, ah1, al1);
        split2h(x02.x, x02.y, ah2, al2);
        split2h(x12.x, x12.y, ah3, al3);
        const uint2* Bh = &g_WcB_hi[kt * 256 + lane];
        const uint2* Bl = &g_WcB_lo[kt * 256 + lane];
        #pragma unroll
        for (int nt = 0; nt < 8; nt++) {
            uint2 bh = Bh[nt * 32];
            uint2 bl = Bl[nt * 32];
            mma_f16(acc[nt], ah0, ah1, ah2, ah3, bh.x, bh.y);
            mma_f16(acc[nt], ah0, ah1, ah2, ah3, bl.x, bl.y);
            mma_f16(acc[nt], al0, al1, al2, al3, bh.x, bh.y);
        }
    }

    if (v0) {
        float dv = g_dinv[r0];
        #pragma unroll
        for (int nt = 0; nt < 8; nt++) {
            int c = nt * 8 + kc;
            __half2 hv = __floats2half2_rn(acc[nt][0] * dv, acc[nt][1] * dv);
            *(__half2*)&g_h16[(size_t)r0 * HID_DIM + c] = hv;
        }
    }
    if (v1) {
        float dv = g_dinv[r1];
        #pragma unroll
        for (int nt = 0; nt < 8; nt++) {
            int c = nt * 8 + kc;
            __half2 hv = __floats2half2_rn(acc[nt][2] * dv, acc[nt][3] * dv);
            *(__half2*)&g_h16[(size_t)r1 * HID_DIM + c] = hv;
        }
    }
}

// ---------------------------------------------------------------------------
// CSR aggregate (atomic-free, fp16 gather) + fused bias/relu:
// agg16[n] = fp16(relu((sum_{src} h16[src] + h16[n]) * dinv[n] + bc))
// ---------------------------------------------------------------------------
__global__ __launch_bounds__(256) void k_aggregate(const float* __restrict__ bc) {
    int tid = threadIdx.x;
    int node = blockIdx.x * 32 + (tid >> 3);
    int sub = tid & 7;
    if (node >= N_NODES) return;
    unsigned gmask = 0xffu << ((tid & 31) & ~7);  // own 8-thread group

    int beg = g_off[node];
    int cnt = g_cnt[node];
    int end = beg + cnt;

    float acc[8];
    {   // self-loop term
        uint4 hv = *(const uint4*)&g_h16[(size_t)node * HID_DIM + sub * 8];
        const __half2* hp = (const __half2*)&hv;
        #pragma unroll
        for (int q = 0; q < 4; q++) {
            float2 f = __half22float2(hp[q]);
            acc[q * 2] = f.x; acc[q * 2 + 1] = f.y;
        }
    }

    int p = beg;
    int full_end = beg + (cnt & ~7);
    for (; p < full_end; p += 8) {
        int mysrc = g_srcbin[p + sub];
        #pragma unroll
        for (int j = 0; j < 8; j++) {
            int s = __shfl_sync(gmask, mysrc, j, 8);
            uint4 hv = *(const uint4*)&g_h16[(size_t)s * HID_DIM + sub * 8];
            const __half2* hp = (const __half2*)&hv;
            #pragma unroll
            for (int q = 0; q < 4; q++) {
                float2 f = __half22float2(hp[q]);
                acc[q * 2] += f.x; acc[q * 2 + 1] += f.y;
            }
        }
    }
    if (p < end) {
        int mye = p + sub;
        int mysrc = (mye < end) ? g_srcbin[mye] : 0;
        int m = end - p;
        #pragma unroll
        for (int j = 0; j < 8; j++) {
            if (j < m) {
                int s = __shfl_sync(gmask, mysrc, j, 8);
                uint4 hv = *(const uint4*)&g_h16[(size_t)s * HID_DIM + sub * 8];
                const __half2* hp = (const __half2*)&hv;
                #pragma unroll
                for (int q = 0; q < 4; q++) {
                    float2 f = __half22float2(hp[q]);
                    acc[q * 2] += f.x; acc[q * 2 + 1] += f.y;
                }
            }
        }
    }

    float dv = g_dinv[node];
    float4 b0 = *(const float4*)&bc[sub * 8];
    float4 b1 = *(const float4*)&bc[sub * 8 + 4];
    float r[8];
    r[0] = fmaxf(acc[0] * dv + b0.x, 0.f);
    r[1] = fmaxf(acc[1] * dv + b0.y, 0.f);
    r[2] = fmaxf(acc[2] * dv + b0.z, 0.f);
    r[3] = fmaxf(acc[3] * dv + b0.w, 0.f);
    r[4] = fmaxf(acc[4] * dv + b1.x, 0.f);
    r[5] = fmaxf(acc[5] * dv + b1.y, 0.f);
    r[6] = fmaxf(acc[6] * dv + b1.z, 0.f);
    r[7] = fmaxf(acc[7] * dv + b1.w, 0.f);
    uint4 ov;
    __half2 p0 = __floats2half2_rn(r[0], r[1]);
    __half2 p1 = __floats2half2_rn(r[2], r[3]);
    __half2 p2 = __floats2half2_rn(r[4], r[5]);
    __half2 p3 = __floats2half2_rn(r[6], r[7]);
    ov.x = *reinterpret_cast<uint32_t*>(&p0);
    ov.y = *reinterpret_cast<uint32_t*>(&p1);
    ov.z = *reinterpret_cast<uint32_t*>(&p2);
    ov.w = *reinterpret_cast<uint32_t*>(&p3);
    *(uint4*)&g_agg16[(size_t)node * HID_DIM + sub * 8] = ov;
}

// ---------------------------------------------------------------------------
// GEMM2 (HMMA f16 2-product): out = agg16 @ Wl + bl
// ---------------------------------------------------------------------------
__global__ __launch_bounds__(256) void k_gemm2_mma(const float* __restrict__ bl,
                                                   float* __restrict__ out) {
    int tid = threadIdx.x, wid = tid >> 5, lane = tid & 31;
    int rowbase = blockIdx.x * 128 + wid * 16;
    int r0 = rowbase + (lane >> 2);
    int r1 = r0 + 8;
    int kc = (lane & 3) * 2;
    bool v0 = r0 < N_NODES, v1 = r1 < N_NODES;

    float acc[16][4];
    #pragma unroll
    for (int nt = 0; nt < 16; nt++)
        #pragma unroll
        for (int i = 0; i < 4; i++) acc[nt][i] = 0.0f;

    #pragma unroll
    for (int kt = 0; kt < 4; kt++) {
        int k0 = kt * 16 + kc;
        uint32_t a0 = 0, a1 = 0, a2 = 0, a3 = 0;
        if (v0) {
            a0 = *(const uint32_t*)&g_agg16[(size_t)r0 * HID_DIM + k0];
            a2 = *(const uint32_t*)&g_agg16[(size_t)r0 * HID_DIM + k0 + 8];
        }
        if (v1) {
            a1 = *(const uint32_t*)&g_agg16[(size_t)r1 * HID_DIM + k0];
            a3 = *(const uint32_t*)&g_agg16[(size_t)r1 * HID_DIM + k0 + 8];
        }
        const uint2* Bh = &g_WlB_hi[kt * 512 + lane];
        const uint2* Bl = &g_WlB_lo[kt * 512 + lane];
        #pragma unroll
        for (int nt = 0; nt < 16; nt++) {
            uint2 bh = Bh[nt * 32];
            uint2 blf = Bl[nt * 32];
            mma_f16(acc[nt], a0, a1, a2, a3, bh.x, bh.y);
            mma_f16(acc[nt], a0, a1, a2, a3, blf.x, blf.y);
        }
    }

    if (v0) {
        #pragma unroll
        for (int nt = 0; nt < 16; nt++) {
            int c = nt * 8 + kc;
            float2 b = *(const float2*)&bl[c];
            *(float2*)&out[(size_t)r0 * OUT_DIM + c] =
                make_float2(acc[nt][0] + b.x, acc[nt][1] + b.y);
        }
    }
    if (v1) {
        #pragma unroll
        for (int nt = 0; nt < 16; nt++) {
            int c = nt * 8 + kc;
            float2 b = *(const float2*)&bl[c];
            *(float2*)&out[(size_t)r1 * OUT_DIM + c] =
                make_float2(acc[nt][2] + b.x, acc[nt][3] + b.y);
        }
    }
}

// ---------------------------------------------------------------------------
// Launch (7 kernels)
// ---------------------------------------------------------------------------
extern "C" void kernel_launch(void* const* d_in, const int* in_sizes, int n_in,
                              void* d_out, int out_size) {
    const float* x  = (const float*)d_in[0];
    const int*   ei = (const int*)d_in[1];
    const float* Wc = (const float*)d_in[2];
    const float* bc = (const float*)d_in[3];
    const float* Wl = (const float*)d_in[4];
    const float* bl = (const float*)d_in[5];
    float* out = (float*)d_out;

    k_init<<<(N_NODES + 255) / 256, 256>>>(Wc, Wl);
    k_count<<<(N_EDGES / 4 + 255) / 256, 256>>>(ei + N_EDGES);
    k_scan_fused<<<SCAN_NB, 256>>>();
    k_bin<<<(N_EDGES / 4 + 255) / 256, 256>>>(ei);

    int grid = (N_NODES + 127) / 128;  // 782
    k_gemm1_mma<<<grid, 256>>>(x);
    k_aggregate<<<(N_NODES + 31) / 32, 256>>>(bc);
    k_gemm2_mma<<<grid, 256>>>(bl, out);
}

// round 10
// speedup vs baseline: 2.9266x; 1.0233x over previous
#include <cuda_runtime.h>
#include <cuda_bf16.h>
#include <cuda_fp16.h>
#include <cstdint>

#define N_NODES 100000
#define N_EDGES 1600000
#define IN_DIM 128
#define HID_DIM 64
#define OUT_DIM 128

#define SCAN_NB 98  // ceil(100000/1024)
#define SCAN_FLAG (1 << 30)

// ---------------------------------------------------------------------------
// Device scratch (no allocations allowed)
// ---------------------------------------------------------------------------
__device__ __half g_h16[N_NODES * HID_DIM];   // h_scaled = (x@Wc)*dinv, fp16
__device__ __half g_agg16[N_NODES * HID_DIM]; // relu(agg*dinv + bc), fp16
__device__ float  g_dinv[N_NODES];
__device__ int    g_cnt[N_NODES];             // in-degree (no self-loop)
__device__ int    g_off[N_NODES];             // CSR row start
__device__ int    g_slot[N_EDGES];            // per-edge slot within dst row
__device__ int    g_bsum[SCAN_NB];            // lookback aggregates (flag bit 30)
__device__ int    g_srcbin[N_EDGES];          // CSR: src per in-edge, by dst

// Prepacked B fragments for mma.sync m16n8k16 (fp16 hi/lo for both GEMMs).
__device__ uint2 g_WcB_hi[8 * 8 * 32];
__device__ uint2 g_WcB_lo[8 * 8 * 32];
__device__ uint2 g_WlB_hi[4 * 16 * 32];
__device__ uint2 g_WlB_lo[4 * 16 * 32];

// ---------------------------------------------------------------------------
// Helpers
// ---------------------------------------------------------------------------
// Split fp32 pair (a,b) -> hi/lo fp16x2 packs (a low half, b high half).
__device__ __forceinline__ void split2h(float a, float b, uint32_t& hi, uint32_t& lo) {
    __half ha = __float2half_rn(a);
    __half hb = __float2half_rn(b);
    __half la = __float2half_rn(a - __half2float(ha));
    __half lb = __float2half_rn(b - __half2float(hb));
    __half2 hpack = __halves2half2(ha, hb);
    __half2 lpack = __halves2half2(la, lb);
    hi = *reinterpret_cast<uint32_t*>(&hpack);
    lo = *reinterpret_cast<uint32_t*>(&lpack);
}

__device__ __forceinline__ void mma_f16(float* c, uint32_t a0, uint32_t a1,
                                        uint32_t a2, uint32_t a3,
                                        uint32_t b0, uint32_t b1) {
    asm volatile(
        "mma.sync.aligned.m16n8k16.row.col.f32.f16.f16.f32 "
        "{%0,%1,%2,%3}, {%4,%5,%6,%7}, {%8,%9}, {%0,%1,%2,%3};"
        : "+f"(c[0]), "+f"(c[1]), "+f"(c[2]), "+f"(c[3])
        : "r"(a0), "r"(a1), "r"(a2), "r"(a3), "r"(b0), "r"(b1));
}

// ---------------------------------------------------------------------------
// Zero counters / lookback state (stream0 head)
// ---------------------------------------------------------------------------
__global__ void k_zero() {
    int t = blockIdx.x * blockDim.x + threadIdx.x;
    if (t < N_NODES) g_cnt[t] = 0;
    if (t < SCAN_NB) g_bsum[t] = 0;
}

// Weight fragment packing (streamB head; independent of CSR chain)
__global__ void k_initw(const float* __restrict__ Wc, const float* __restrict__ Wl) {
    int t = blockIdx.x * blockDim.x + threadIdx.x;
    if (t < 2048) {  // Wc: 8 kt x 8 nt x 32 lanes
        int lane = t & 31, nt = (t >> 5) & 7, kt = t >> 8;
        int k0 = kt * 16 + (lane & 3) * 2;
        int n = nt * 8 + (lane >> 2);
        uint2 hi, lo;
        split2h(Wc[k0 * HID_DIM + n], Wc[(k0 + 1) * HID_DIM + n], hi.x, lo.x);
        split2h(Wc[(k0 + 8) * HID_DIM + n], Wc[(k0 + 9) * HID_DIM + n], hi.y, lo.y);
        g_WcB_hi[t] = hi;
        g_WcB_lo[t] = lo;
    } else if (t < 4096) {  // Wl: 4 kt x 16 nt x 32 lanes
        int u = t - 2048;
        int lane = u & 31, nt = (u >> 5) & 15, kt = u >> 9;
        int k0 = kt * 16 + (lane & 3) * 2;
        int n = nt * 8 + (lane >> 2);
        uint2 hi, lo;
        split2h(Wl[k0 * OUT_DIM + n], Wl[(k0 + 1) * OUT_DIM + n], hi.x, lo.x);
        split2h(Wl[(k0 + 8) * OUT_DIM + n], Wl[(k0 + 9) * OUT_DIM + n], hi.y, lo.y);
        g_WlB_hi[u] = hi;
        g_WlB_lo[u] = lo;
    }
}

// Count in-degrees AND record each edge's slot within its dst row.
__global__ void k_count(const int* __restrict__ dst) {
    int e4 = blockIdx.x * blockDim.x + threadIdx.x;
    if (e4 >= N_EDGES / 4) return;
    int4 d = ((const int4*)dst)[e4];
    int4 s;
    s.x = atomicAdd(&g_cnt[d.x], 1);
    s.y = atomicAdd(&g_cnt[d.y], 1);
    s.z = atomicAdd(&g_cnt[d.z], 1);
    s.w = atomicAdd(&g_cnt[d.w], 1);
    ((int4*)g_slot)[e4] = s;
}

// ---------------------------------------------------------------------------
// Fused exclusive scan (decoupled lookback) + dinv.
// ---------------------------------------------------------------------------
__global__ __launch_bounds__(256) void k_scan_fused() {
    __shared__ int sh[256];
    int t = threadIdx.x, b = blockIdx.x;
    int base = b * 1024 + t * 4;
    int v[4];
    #pragma unroll
    for (int i = 0; i < 4; i++)
        v[i] = (base + i < N_NODES) ? g_cnt[base + i] : 0;
    int s = v[0] + v[1] + v[2] + v[3];
    sh[t] = s;
    __syncthreads();
    #pragma unroll
    for (int off = 1; off < 256; off <<= 1) {
        int add = (t >= off) ? sh[t - off] : 0;
        __syncthreads();
        sh[t] += add;
        __syncthreads();
    }
    if (t == 255) atomicExch(&g_bsum[b], sh[255] | SCAN_FLAG);
    int ex = sh[t] - s;  // exclusive prefix within block

    int part = 0;
    if (t < b) {
        int val;
        do { val = atomicAdd(&g_bsum[t], 0); } while (!(val & SCAN_FLAG));
        part = val & ~SCAN_FLAG;
    }
    __syncthreads();
    sh[t] = part;
    __syncthreads();
    #pragma unroll
    for (int off = 128; off >= 1; off >>= 1) {
        if (t < off) sh[t] += sh[t + off];
        __syncthreads();
    }
    int boff = sh[0];

    int run = ex + boff;
    #pragma unroll
    for (int i = 0; i < 4; i++) {
        int idx = base + i;
        if (idx < N_NODES) {
            g_off[idx] = run;
            g_dinv[idx] = rsqrtf((float)(v[i] + 1));
            run += v[i];
        }
    }
}

// Bin edges by dst — atomic-free: pos = off[dst] + slot.
__global__ void k_bin(const int* __restrict__ ei) {
    int e4 = blockIdx.x * blockDim.x + threadIdx.x;
    if (e4 >= N_EDGES / 4) return;
    int4 s = ((const int4*)ei)[e4];
    int4 d = ((const int4*)(ei + N_EDGES))[e4];
    int4 sl = ((const int4*)g_slot)[e4];
    g_srcbin[__ldg(&g_off[d.x]) + sl.x] = s.x;
    g_srcbin[__ldg(&g_off[d.y]) + sl.y] = s.y;
    g_srcbin[__ldg(&g_off[d.z]) + sl.z] = s.z;
    g_srcbin[__ldg(&g_off[d.w]) + sl.w] = s.w;
}

// ---------------------------------------------------------------------------
// GEMM1 (HMMA fp16 3-product): g_h16 = fp16((x @ Wc) * dinv[row])
// ---------------------------------------------------------------------------
__global__ __launch_bounds__(256) void k_gemm1_mma(const float* __restrict__ x) {
    int tid = threadIdx.x, wid = tid >> 5, lane = tid & 31;
    int rowbase = blockIdx.x * 128 + wid * 16;
    int r0 = rowbase + (lane >> 2);
    int r1 = r0 + 8;
    int kc = (lane & 3) * 2;
    bool v0 = r0 < N_NODES, v1 = r1 < N_NODES;

    float acc[8][4];
    #pragma unroll
    for (int nt = 0; nt < 8; nt++)
        #pragma unroll
        for (int i = 0; i < 4; i++) acc[nt][i] = 0.0f;

    const float2 z2 = make_float2(0.f, 0.f);
    #pragma unroll
    for (int kt = 0; kt < 8; kt++) {
        int k0 = kt * 16 + kc;
        float2 x00 = v0 ? *(const float2*)&x[(size_t)r0 * IN_DIM + k0] : z2;
        float2 x02 = v0 ? *(const float2*)&x[(size_t)r0 * IN_DIM + k0 + 8] : z2;
        float2 x10 = v1 ? *(const float2*)&x[(size_t)r1 * IN_DIM + k0] : z2;
        float2 x12 = v1 ? *(const float2*)&x[(size_t)r1 * IN_DIM + k0 + 8] : z2;
        uint32_t ah0, al0, ah1, al1, ah2, al2, ah3, al3;
        split2h(x00.x, x00.y, ah0, al0);
        split2h(x10.x, x10.y, ah1, al1);
        split2h(x02.x, x02.y, ah2, al2);
        split2h(x12.x, x12.y, ah3, al3);
        const uint2* Bh = &g_WcB_hi[kt * 256 + lane];
        const uint2* Bl = &g_WcB_lo[kt * 256 + lane];
        #pragma unroll
        for (int nt = 0; nt < 8; nt++) {
            uint2 bh = Bh[nt * 32];
            uint2 bl = Bl[nt * 32];
            mma_f16(acc[nt], ah0, ah1, ah2, ah3, bh.x, bh.y);
            mma_f16(acc[nt], ah0, ah1, ah2, ah3, bl.x, bl.y);
            mma_f16(acc[nt], al0, al1, al2, al3, bh.x, bh.y);
        }
    }

    if (v0) {
        float dv = g_dinv[r0];
        #pragma unroll
        for (int nt = 0; nt < 8; nt++) {
            int c = nt * 8 + kc;
            __half2 hv = __floats2half2_rn(acc[nt][0] * dv, acc[nt][1] * dv);
            *(__half2*)&g_h16[(size_t)r0 * HID_DIM + c] = hv;
        }
    }
    if (v1) {
        float dv = g_dinv[r1];
        #pragma unroll
        for (int nt = 0; nt < 8; nt++) {
            int c = nt * 8 + kc;
            __half2 hv = __floats2half2_rn(acc[nt][2] * dv, acc[nt][3] * dv);
            *(__half2*)&g_h16[(size_t)r1 * HID_DIM + c] = hv;
        }
    }
}

// ---------------------------------------------------------------------------
// CSR aggregate (atomic-free, fp16 gather) + fused bias/relu:
// agg16[n] = fp16(relu((sum_{src} h16[src] + h16[n]) * dinv[n] + bc))
// ---------------------------------------------------------------------------
__global__ __launch_bounds__(256) void k_aggregate(const float* __restrict__ bc) {
    int tid = threadIdx.x;
    int node = blockIdx.x * 32 + (tid >> 3);
    int sub = tid & 7;
    if (node >= N_NODES) return;
    unsigned gmask = 0xffu << ((tid & 31) & ~7);  // own 8-thread group

    int beg = g_off[node];
    int cnt = g_cnt[node];
    int end = beg + cnt;

    float acc[8];
    {   // self-loop term
        uint4 hv = *(const uint4*)&g_h16[(size_t)node * HID_DIM + sub * 8];
        const __half2* hp = (const __half2*)&hv;
        #pragma unroll
        for (int q = 0; q < 4; q++) {
            float2 f = __half22float2(hp[q]);
            acc[q * 2] = f.x; acc[q * 2 + 1] = f.y;
        }
    }

    int p = beg;
    int full_end = beg + (cnt & ~7);
    for (; p < full_end; p += 8) {
        int mysrc = g_srcbin[p + sub];
        #pragma unroll
        for (int j = 0; j < 8; j++) {
            int s = __shfl_sync(gmask, mysrc, j, 8);
            uint4 hv = *(const uint4*)&g_h16[(size_t)s * HID_DIM + sub * 8];
            const __half2* hp = (const __half2*)&hv;
            #pragma unroll
            for (int q = 0; q < 4; q++) {
                float2 f = __half22float2(hp[q]);
                acc[q * 2] += f.x; acc[q * 2 + 1] += f.y;
            }
        }
    }
    if (p < end) {
        int mye = p + sub;
        int mysrc = (mye < end) ? g_srcbin[mye] : 0;
        int m = end - p;
        #pragma unroll
        for (int j = 0; j < 8; j++) {
            if (j < m) {
                int s = __shfl_sync(gmask, mysrc, j, 8);
                uint4 hv = *(const uint4*)&g_h16[(size_t)s * HID_DIM + sub * 8];
                const __half2* hp = (const __half2*)&hv;
                #pragma unroll
                for (int q = 0; q < 4; q++) {
                    float2 f = __half22float2(hp[q]);
                    acc[q * 2] += f.x; acc[q * 2 + 1] += f.y;
                }
            }
        }
    }

    float dv = g_dinv[node];
    float4 b0 = *(const float4*)&bc[sub * 8];
    float4 b1 = *(const float4*)&bc[sub * 8 + 4];
    float r[8];
    r[0] = fmaxf(acc[0] * dv + b0.x, 0.f);
    r[1] = fmaxf(acc[1] * dv + b0.y, 0.f);
    r[2] = fmaxf(acc[2] * dv + b0.z, 0.f);
    r[3] = fmaxf(acc[3] * dv + b0.w, 0.f);
    r[4] = fmaxf(acc[4] * dv + b1.x, 0.f);
    r[5] = fmaxf(acc[5] * dv + b1.y, 0.f);
    r[6] = fmaxf(acc[6] * dv + b1.z, 0.f);
    r[7] = fmaxf(acc[7] * dv + b1.w, 0.f);
    uint4 ov;
    __half2 p0 = __floats2half2_rn(r[0], r[1]);
    __half2 p1 = __floats2half2_rn(r[2], r[3]);
    __half2 p2 = __floats2half2_rn(r[4], r[5]);
    __half2 p3 = __floats2half2_rn(r[6], r[7]);
    ov.x = *reinterpret_cast<uint32_t*>(&p0);
    ov.y = *reinterpret_cast<uint32_t*>(&p1);
    ov.z = *reinterpret_cast<uint32_t*>(&p2);
    ov.w = *reinterpret_cast<uint32_t*>(&p3);
    *(uint4*)&g_agg16[(size_t)node * HID_DIM + sub * 8] = ov;
}

// ---------------------------------------------------------------------------
// GEMM2 (HMMA f16 2-product): out = agg16 @ Wl + bl
// ---------------------------------------------------------------------------
__global__ __launch_bounds__(256) void k_gemm2_mma(const float* __restrict__ bl,
                                                   float* __restrict__ out) {
    int tid = threadIdx.x, wid = tid >> 5, lane = tid & 31;
    int rowbase = blockIdx.x * 128 + wid * 16;
    int r0 = rowbase + (lane >> 2);
    int r1 = r0 + 8;
    int kc = (lane & 3) * 2;
    bool v0 = r0 < N_NODES, v1 = r1 < N_NODES;

    float acc[16][4];
    #pragma unroll
    for (int nt = 0; nt < 16; nt++)
        #pragma unroll
        for (int i = 0; i < 4; i++) acc[nt][i] = 0.0f;

    #pragma unroll
    for (int kt = 0; kt < 4; kt++) {
        int k0 = kt * 16 + kc;
        uint32_t a0 = 0, a1 = 0, a2 = 0, a3 = 0;
        if (v0) {
            a0 = *(const uint32_t*)&g_agg16[(size_t)r0 * HID_DIM + k0];
            a2 = *(const uint32_t*)&g_agg16[(size_t)r0 * HID_DIM + k0 + 8];
        }
        if (v1) {
            a1 = *(const uint32_t*)&g_agg16[(size_t)r1 * HID_DIM + k0];
            a3 = *(const uint32_t*)&g_agg16[(size_t)r1 * HID_DIM + k0 + 8];
        }
        const uint2* Bh = &g_WlB_hi[kt * 512 + lane];
        const uint2* Bl = &g_WlB_lo[kt * 512 + lane];
        #pragma unroll
        for (int nt = 0; nt < 16; nt++) {
            uint2 bh = Bh[nt * 32];
            uint2 blf = Bl[nt * 32];
            mma_f16(acc[nt], a0, a1, a2, a3, bh.x, bh.y);
            mma_f16(acc[nt], a0, a1, a2, a3, blf.x, blf.y);
        }
    }

    if (v0) {
        #pragma unroll
        for (int nt = 0; nt < 16; nt++) {
            int c = nt * 8 + kc;
            float2 b = *(const float2*)&bl[c];
            *(float2*)&out[(size_t)r0 * OUT_DIM + c] =
                make_float2(acc[nt][0] + b.x, acc[nt][1] + b.y);
        }
    }
    if (v1) {
        #pragma unroll
        for (int nt = 0; nt < 16; nt++) {
            int c = nt * 8 + kc;
            float2 b = *(const float2*)&bl[c];
            *(float2*)&out[(size_t)r1 * OUT_DIM + c] =
                make_float2(acc[nt][2] + b.x, acc[nt][3] + b.y);
        }
    }
}

// ---------------------------------------------------------------------------
// Launch — two-stream fork/join:
//   stream0: zero -> count -> scan -> bin -> [join gemm1] aggregate -> gemm2
//   sB:      [fork] initw -> [wait scan] gemm1
// Streams/events created on first (uncaptured) call; capture uses the
// standard event fork/join pattern.
// ---------------------------------------------------------------------------
extern "C" void kernel_launch(void* const* d_in, const int* in_sizes, int n_in,
                              void* d_out, int out_size) {
    const float* x  = (const float*)d_in[0];
    const int*   ei = (const int*)d_in[1];
    const float* Wc = (const float*)d_in[2];
    const float* bc = (const float*)d_in[3];
    const float* Wl = (const float*)d_in[4];
    const float* bl = (const float*)d_in[5];
    float* out = (float*)d_out;

    static cudaStream_t sB = nullptr;
    static cudaEvent_t evFork, evScan, evB;
    if (sB == nullptr) {
        cudaStreamCreateWithFlags(&sB, cudaStreamNonBlocking);
        cudaEventCreateWithFlags(&evFork, cudaEventDisableTiming);
        cudaEventCreateWithFlags(&evScan, cudaEventDisableTiming);
        cudaEventCreateWithFlags(&evB, cudaEventDisableTiming);
    }

    // Fork sB off stream 0
    cudaEventRecord(evFork, 0);
    cudaStreamWaitEvent(sB, evFork, 0);

    // sB: weight packing (independent of CSR chain)
    k_initw<<<16, 256, 0, sB>>>(Wc, Wl);

    // stream0: CSR chain
    k_zero<<<(N_NODES + 255) / 256, 256>>>();
    k_count<<<(N_EDGES / 4 + 255) / 256, 256>>>(ei + N_EDGES);
    k_scan_fused<<<SCAN_NB, 256>>>();

    // gemm1 on sB once dinv is ready; bin runs concurrently on stream0
    cudaEventRecord(evScan, 0);
    cudaStreamWaitEvent(sB, evScan, 0);
    int grid = (N_NODES + 127) / 128;  // 782
    k_gemm1_mma<<<grid, 256, 0, sB>>>(x);
    cudaEventRecord(evB, sB);

    k_bin<<<(N_EDGES / 4 + 255) / 256, 256>>>(ei);

    // Join: aggregate needs bin (stream0) AND gemm1 (sB)
    cudaStreamWaitEvent(0, evB, 0);
    k_aggregate<<<(N_NODES + 31) / 32, 256>>>(bc);
    k_gemm2_mma<<<grid, 256>>>(bl, out);
}